// round 1
// baseline (speedup 1.0000x reference)
#include <cuda_runtime.h>
#include <cuda_bf16.h>

// Problem constants
#define Bq 32
#define Tt 784
#define Cc 384
#define NHh 6
#define HDd 64
#define Mm (Bq * Tt)          // 25088
#define IMG_H 28
#define IMG_W 28
#define SCALE_F 0.05103103630798288f   // 384^-0.5

// ---------------------------------------------------------------------------
// Scratch (device globals: allowed; no runtime allocation)
// ---------------------------------------------------------------------------
__device__ float g_qt[(size_t)Mm * Cc];
__device__ float g_kt[(size_t)Mm * Cc];
__device__ float g_vt[(size_t)Mm * Cc];
__device__ float g_q[(size_t)Mm * Cc];   // [B, NH, T, HD]
__device__ float g_k[(size_t)Mm * Cc];
__device__ float g_v[(size_t)Mm * Cc];
__device__ float g_o[(size_t)Mm * Cc];   // [B, T, C]

// ---------------------------------------------------------------------------
// Kernel 1: depthwise 3x3 conv + eval BN for q/k/v in one pass
// x: [B, T, C]; conv_w: [C,1,3,3]; outputs g_qt/g_kt/g_vt [B,T,C]
// ---------------------------------------------------------------------------
__global__ void __launch_bounds__(256) convbn_kernel(
    const float* __restrict__ x,
    const float* __restrict__ cwq, const float* __restrict__ gq,
    const float* __restrict__ beq, const float* __restrict__ meq,
    const float* __restrict__ vaq,
    const float* __restrict__ cwk, const float* __restrict__ gk,
    const float* __restrict__ bek, const float* __restrict__ mek,
    const float* __restrict__ vak,
    const float* __restrict__ cwv, const float* __restrict__ gv,
    const float* __restrict__ bev, const float* __restrict__ mev,
    const float* __restrict__ vav)
{
    int idx = blockIdx.x * 256 + threadIdx.x;
    if (idx >= Mm * Cc) return;
    int c  = idx % Cc;
    int bt = idx / Cc;
    int t  = bt % Tt;
    int b  = bt / Tt;
    int y  = t / IMG_W;
    int xp = t % IMG_W;

    float vals[9];
#pragma unroll
    for (int dy = 0; dy < 3; dy++) {
#pragma unroll
        for (int dx = 0; dx < 3; dx++) {
            int yy = y + dy - 1, xx = xp + dx - 1;
            bool in = (yy >= 0) && (yy < IMG_H) && (xx >= 0) && (xx < IMG_W);
            vals[dy * 3 + dx] =
                in ? x[((size_t)b * Tt + yy * IMG_W + xx) * Cc + c] : 0.f;
        }
    }

    {
        float acc = 0.f;
#pragma unroll
        for (int i = 0; i < 9; i++) acc += vals[i] * cwq[c * 9 + i];
        float inv = gq[c] * rsqrtf(vaq[c] + 1e-5f);
        g_qt[idx] = acc * inv + (beq[c] - meq[c] * inv);
    }
    {
        float acc = 0.f;
#pragma unroll
        for (int i = 0; i < 9; i++) acc += vals[i] * cwk[c * 9 + i];
        float inv = gk[c] * rsqrtf(vak[c] + 1e-5f);
        g_kt[idx] = acc * inv + (bek[c] - mek[c] * inv);
    }
    {
        float acc = 0.f;
#pragma unroll
        for (int i = 0; i < 9; i++) acc += vals[i] * cwv[c * 9 + i];
        float inv = gv[c] * rsqrtf(vav[c] + 1e-5f);
        g_vt[idx] = acc * inv + (bev[c] - mev[c] * inv);
    }
}

// ---------------------------------------------------------------------------
// SGEMM NT: C[m,n] = sum_k A[m,k] * W[n,k].  M x 384 x 384.
// 64x64 block tile, K-tile 16, 256 threads, 4x4 micro-tile per thread.
// ---------------------------------------------------------------------------
__device__ __forceinline__ void gemm_tile_body(
    const float* __restrict__ A, const float* __restrict__ W,
    float acc[4][4], float (*As)[64], float (*Bs)[64],
    int bm, int bn, int tid)
{
    int lr = tid >> 2;       // 0..63 : tile row being loaded
    int lk4 = tid & 3;       // which float4 of the 16-wide k slab
    int tx = tid & 15;       // n group
    int ty = tid >> 4;       // m group

    for (int k0 = 0; k0 < Cc; k0 += 16) {
        float4 a4 = *(const float4*)(A + (size_t)(bm + lr) * Cc + k0 + lk4 * 4);
        float4 b4 = *(const float4*)(W + (size_t)(bn + lr) * Cc + k0 + lk4 * 4);
        __syncthreads();
        As[lk4 * 4 + 0][lr] = a4.x;
        As[lk4 * 4 + 1][lr] = a4.y;
        As[lk4 * 4 + 2][lr] = a4.z;
        As[lk4 * 4 + 3][lr] = a4.w;
        Bs[lk4 * 4 + 0][lr] = b4.x;
        Bs[lk4 * 4 + 1][lr] = b4.y;
        Bs[lk4 * 4 + 2][lr] = b4.z;
        Bs[lk4 * 4 + 3][lr] = b4.w;
        __syncthreads();
#pragma unroll
        for (int kk = 0; kk < 16; kk++) {
            float4 av = *(const float4*)&As[kk][ty * 4];
            float4 bv = *(const float4*)&Bs[kk][tx * 4];
            float a[4] = {av.x, av.y, av.z, av.w};
            float bb[4] = {bv.x, bv.y, bv.z, bv.w};
#pragma unroll
            for (int i = 0; i < 4; i++)
#pragma unroll
                for (int j = 0; j < 4; j++) acc[i][j] += a[i] * bb[j];
        }
    }
}

// Q/K/V projection: A = g_qt/kt/vt, output scattered to [B, NH, T, HD]
__global__ void __launch_bounds__(256) sgemm_qkv_kernel(
    const float* __restrict__ W, int which)
{
    __shared__ float As[16][64];
    __shared__ float Bs[16][64];
    const float* A = (which == 0) ? g_qt : (which == 1) ? g_kt : g_vt;
    float* O       = (which == 0) ? g_q  : (which == 1) ? g_k  : g_v;

    int bm = blockIdx.x * 64, bn = blockIdx.y * 64;
    int tid = threadIdx.x;
    float acc[4][4] = {};
    gemm_tile_body(A, W, acc, As, Bs, bm, bn, tid);

    int tx = tid & 15, ty = tid >> 4;
    int h = bn >> 6;                 // bn multiple of 64 == HD -> fixed head
    int d = tx * 4;                  // column within head, float4-aligned
#pragma unroll
    for (int i = 0; i < 4; i++) {
        int m = bm + ty * 4 + i;
        int b = m / Tt, t = m % Tt;
        float4 v4 = make_float4(acc[i][0], acc[i][1], acc[i][2], acc[i][3]);
        *(float4*)(O + (((size_t)b * NHh + h) * Tt + t) * HDd + d) = v4;
    }
}

// Output projection: A = g_o, plain layout + bias
__global__ void __launch_bounds__(256) sgemm_proj_kernel(
    const float* __restrict__ W, const float* __restrict__ bias,
    float* __restrict__ out)
{
    __shared__ float As[16][64];
    __shared__ float Bs[16][64];
    int bm = blockIdx.x * 64, bn = blockIdx.y * 64;
    int tid = threadIdx.x;
    float acc[4][4] = {};
    gemm_tile_body(g_o, W, acc, As, Bs, bm, bn, tid);

    int tx = tid & 15, ty = tid >> 4;
    int n = bn + tx * 4;
    float4 bsv = *(const float4*)(bias + n);
#pragma unroll
    for (int i = 0; i < 4; i++) {
        int m = bm + ty * 4 + i;
        float4 v4 = make_float4(acc[i][0] + bsv.x, acc[i][1] + bsv.y,
                                acc[i][2] + bsv.z, acc[i][3] + bsv.w);
        *(float4*)(out + (size_t)m * Cc + n) = v4;
    }
}

// ---------------------------------------------------------------------------
// Flash-style attention (fp32). One block = one (b,h) x 128 query rows.
// K/V tiles of 64 keys staged in SMEM (broadcast reads -> conflict-free).
// Online softmax in 16-key register chunks. Output written to g_o [B,T,C].
// ---------------------------------------------------------------------------
__global__ void __launch_bounds__(128) attn_kernel()
{
    __shared__ float ksh[64][64];
    __shared__ float vsh[64][64];

    int bh = blockIdx.x;                        // 0..191
    int row = blockIdx.y * 128 + threadIdx.x;   // query index
    bool valid = row < Tt;

    const float* Qb = g_q + (size_t)bh * Tt * HDd;
    const float* Kb = g_k + (size_t)bh * Tt * HDd;
    const float* Vb = g_v + (size_t)bh * Tt * HDd;

    float q[64];
    if (valid) {
#pragma unroll
        for (int d4 = 0; d4 < 16; d4++) {
            float4 t4 = *(const float4*)(Qb + (size_t)row * HDd + d4 * 4);
            q[d4 * 4 + 0] = t4.x * SCALE_F;
            q[d4 * 4 + 1] = t4.y * SCALE_F;
            q[d4 * 4 + 2] = t4.z * SCALE_F;
            q[d4 * 4 + 3] = t4.w * SCALE_F;
        }
    }

    float o[64];
#pragma unroll
    for (int d = 0; d < 64; d++) o[d] = 0.f;
    float mrun = -1e30f, lrun = 0.f;

    for (int kt0 = 0; kt0 < Tt; kt0 += 64) {
        int jn = (Tt - kt0 < 64) ? (Tt - kt0) : 64;   // 64 or 16
        __syncthreads();
        for (int i = threadIdx.x; i < (jn * 64) / 4; i += 128) {
            int r = i >> 4, c4 = i & 15;
            *(float4*)&ksh[r][c4 * 4] =
                *(const float4*)(Kb + (size_t)(kt0 + r) * HDd + c4 * 4);
            *(float4*)&vsh[r][c4 * 4] =
                *(const float4*)(Vb + (size_t)(kt0 + r) * HDd + c4 * 4);
        }
        __syncthreads();
        if (valid) {
            for (int jc = 0; jc < jn; jc += 16) {
                float s[16];
                float tmax = -1e30f;
#pragma unroll
                for (int jj = 0; jj < 16; jj++) {
                    float acc = 0.f;
#pragma unroll
                    for (int d = 0; d < 64; d++)
                        acc += q[d] * ksh[jc + jj][d];
                    s[jj] = acc;
                    tmax = fmaxf(tmax, acc);
                }
                if (tmax > mrun) {
                    float sc = __expf(mrun - tmax);
                    mrun = tmax;
                    lrun *= sc;
#pragma unroll
                    for (int d = 0; d < 64; d++) o[d] *= sc;
                }
#pragma unroll
                for (int jj = 0; jj < 16; jj++) {
                    float p = __expf(s[jj] - mrun);
                    lrun += p;
#pragma unroll
                    for (int d = 0; d < 64; d++)
                        o[d] += p * vsh[jc + jj][d];
                }
            }
        }
    }

    if (valid) {
        float rcp = 1.f / lrun;
        int b = bh / NHh, h = bh % NHh;
        float* op = g_o + ((size_t)b * Tt + row) * Cc + h * HDd;
#pragma unroll
        for (int d4 = 0; d4 < 16; d4++) {
            float4 t4 = make_float4(o[d4 * 4 + 0] * rcp, o[d4 * 4 + 1] * rcp,
                                    o[d4 * 4 + 2] * rcp, o[d4 * 4 + 3] * rcp);
            *(float4*)(op + d4 * 4) = t4;
        }
    }
}

// ---------------------------------------------------------------------------
// kernel_launch
// ---------------------------------------------------------------------------
extern "C" void kernel_launch(void* const* d_in, const int* in_sizes, int n_in,
                              void* d_out, int out_size)
{
    // inputs per setup_inputs order:
    // 0:x, [1:h, 2:w scalars if present],
    // then 3 groups of (conv_w, gamma, beta, mean, var) for q/k/v,
    // then w_q, w_k, w_v, w_proj, b_proj
    int base = 1;
    if (n_in >= 3 && in_sizes[1] == 1 && in_sizes[2] == 1) base = 3;

    const float* x = (const float*)d_in[0];
    const float* cw[3];
    const float* ga[3];
    const float* be[3];
    const float* me[3];
    const float* va[3];
    for (int i = 0; i < 3; i++) {
        cw[i] = (const float*)d_in[base + 5 * i + 0];
        ga[i] = (const float*)d_in[base + 5 * i + 1];
        be[i] = (const float*)d_in[base + 5 * i + 2];
        me[i] = (const float*)d_in[base + 5 * i + 3];
        va[i] = (const float*)d_in[base + 5 * i + 4];
    }
    const float* w_q    = (const float*)d_in[base + 15];
    const float* w_k    = (const float*)d_in[base + 16];
    const float* w_v    = (const float*)d_in[base + 17];
    const float* w_proj = (const float*)d_in[base + 18];
    const float* b_proj = (const float*)d_in[base + 19];
    float* out = (float*)d_out;

    convbn_kernel<<<(Mm * Cc + 255) / 256, 256>>>(
        x,
        cw[0], ga[0], be[0], me[0], va[0],
        cw[1], ga[1], be[1], me[1], va[1],
        cw[2], ga[2], be[2], me[2], va[2]);

    dim3 gg(Mm / 64, Cc / 64);
    sgemm_qkv_kernel<<<gg, 256>>>(w_q, 0);
    sgemm_qkv_kernel<<<gg, 256>>>(w_k, 1);
    sgemm_qkv_kernel<<<gg, 256>>>(w_v, 2);

    attn_kernel<<<dim3(Bq * NHh, (Tt + 127) / 128), 128>>>();

    sgemm_proj_kernel<<<gg, 256>>>(w_proj, b_proj, out);
}

// round 2
// speedup vs baseline: 1.1492x; 1.1492x over previous
#include <cuda_runtime.h>
#include <cuda_bf16.h>
#include <cstdint>

// Problem constants
#define Bq 32
#define Tt 784
#define Cc 384
#define NHh 6
#define HDd 64
#define Mm (Bq * Tt)          // 25088
#define TP 832                // T padded to 13*64
#define BH (Bq * NHh)         // 192
#define IMG_H 28
#define IMG_W 28
#define SCALE_F 0.05103103630798288f   // 384^-0.5

// ---------------------------------------------------------------------------
// Scratch (__device__ globals: zero-initialized at module load; padded regions
// are never written, so they stay zero across graph replays)
// ---------------------------------------------------------------------------
__device__ float g_qt[(size_t)Mm * Cc];
__device__ float g_kt[(size_t)Mm * Cc];
__device__ float g_vt[(size_t)Mm * Cc];
__device__ float g_qp[(size_t)BH * TP * HDd];  // [bh][t(pad)][d], pre-scaled
__device__ float g_kp[(size_t)BH * TP * HDd];  // [bh][t(pad)][d]
__device__ float g_vT[(size_t)BH * HDd * TP];  // [bh][d][t(pad)]  (transposed)
__device__ float g_s [(size_t)BH * TP * TP];   // scores / probs
__device__ float g_o [(size_t)Mm * Cc];        // attention out [b,t,c]

// ---------------------------------------------------------------------------
// Kernel 1: depthwise 3x3 conv + eval BN for q/k/v in one pass
// ---------------------------------------------------------------------------
__global__ void __launch_bounds__(256) convbn_kernel(
    const float* __restrict__ x,
    const float* __restrict__ cwq, const float* __restrict__ gq,
    const float* __restrict__ beq, const float* __restrict__ meq,
    const float* __restrict__ vaq,
    const float* __restrict__ cwk, const float* __restrict__ gk,
    const float* __restrict__ bek, const float* __restrict__ mek,
    const float* __restrict__ vak,
    const float* __restrict__ cwv, const float* __restrict__ gv,
    const float* __restrict__ bev, const float* __restrict__ mev,
    const float* __restrict__ vav)
{
    int idx = blockIdx.x * 256 + threadIdx.x;
    if (idx >= Mm * Cc) return;
    int c  = idx % Cc;
    int bt = idx / Cc;
    int t  = bt % Tt;
    int b  = bt / Tt;
    int y  = t / IMG_W;
    int xp = t % IMG_W;

    float vals[9];
#pragma unroll
    for (int dy = 0; dy < 3; dy++) {
#pragma unroll
        for (int dx = 0; dx < 3; dx++) {
            int yy = y + dy - 1, xx = xp + dx - 1;
            bool in = (yy >= 0) && (yy < IMG_H) && (xx >= 0) && (xx < IMG_W);
            vals[dy * 3 + dx] =
                in ? x[((size_t)b * Tt + yy * IMG_W + xx) * Cc + c] : 0.f;
        }
    }
    {
        float acc = 0.f;
#pragma unroll
        for (int i = 0; i < 9; i++) acc += vals[i] * cwq[c * 9 + i];
        float inv = gq[c] * rsqrtf(vaq[c] + 1e-5f);
        g_qt[idx] = acc * inv + (beq[c] - meq[c] * inv);
    }
    {
        float acc = 0.f;
#pragma unroll
        for (int i = 0; i < 9; i++) acc += vals[i] * cwk[c * 9 + i];
        float inv = gk[c] * rsqrtf(vak[c] + 1e-5f);
        g_kt[idx] = acc * inv + (bek[c] - mek[c] * inv);
    }
    {
        float acc = 0.f;
#pragma unroll
        for (int i = 0; i < 9; i++) acc += vals[i] * cwv[c * 9 + i];
        float inv = gv[c] * rsqrtf(vav[c] + 1e-5f);
        g_vt[idx] = acc * inv + (bev[c] - mev[c] * inv);
    }
}

// ---------------------------------------------------------------------------
// tf32 mma building blocks
// ---------------------------------------------------------------------------
__device__ __forceinline__ uint32_t f2tf32(float f) {
    uint32_t u;
    asm("cvt.rna.tf32.f32 %0, %1;" : "=r"(u) : "f"(f));
    return u;
}

__device__ __forceinline__ void mma_tf32(float c[4],
    uint32_t a0, uint32_t a1, uint32_t a2, uint32_t a3,
    uint32_t b0, uint32_t b1)
{
    asm volatile(
        "mma.sync.aligned.m16n8k8.row.col.f32.tf32.tf32.f32 "
        "{%0,%1,%2,%3}, {%4,%5,%6,%7}, {%8,%9}, {%0,%1,%2,%3};"
        : "+f"(c[0]), "+f"(c[1]), "+f"(c[2]), "+f"(c[3])
        : "r"(a0), "r"(a1), "r"(a2), "r"(a3), "r"(b0), "r"(b1));
}

#define SMS (64 * 33)   // one 64x32 tile, padded rows (uints)

__device__ __forceinline__ void stage_store(uint32_t* dst, float4 a, float4 b) {
    dst[0]  = f2tf32(a.x); dst[1]  = f2tf32(a.y);
    dst[2]  = f2tf32(a.z); dst[3]  = f2tf32(a.w);
    dst[16] = f2tf32(b.x); dst[17] = f2tf32(b.y);
    dst[18] = f2tf32(b.z); dst[19] = f2tf32(b.w);
}

// NT GEMM core: computes 64x64 tile of A(MxK,row) * B(NxK,row)^T at (bm,bn).
// 256 threads, 8 warps as 4(m) x 2(n); warp tile 16x32; BK=32 double-buffered.
// acc[j][0..3] per n-subtile j: {(r0,n0),(r0,n0+1),(r1,n0),(r1,n0+1)}.
__device__ __forceinline__ void gemm_core(
    const float* __restrict__ A, const float* __restrict__ B,
    int lda, int ldb, int K, int bm, int bn,
    uint32_t* As, uint32_t* Bs, float acc[4][4])
{
    const int tid  = threadIdx.x;
    const int lane = tid & 31;
    const int warp = tid >> 5;
    const int wm   = (warp & 3) * 16;
    const int wn   = (warp >> 2) * 32;
    const int lrow = tid >> 2;          // 0..63
    const int lc4  = (tid & 3) * 4;     // 0,4,8,12
    const int g    = lane >> 2;         // 0..7
    const int tq   = lane & 3;          // 0..3
    const int nk   = K >> 5;

    const float* Ag = A + (size_t)(bm + lrow) * lda + lc4;
    const float* Bg = B + (size_t)(bn + lrow) * ldb + lc4;

    float4 a0v = *(const float4*)Ag;
    float4 a1v = *(const float4*)(Ag + 16);
    float4 b0v = *(const float4*)Bg;
    float4 b1v = *(const float4*)(Bg + 16);
    stage_store(As + lrow * 33 + lc4, a0v, a1v);
    stage_store(Bs + lrow * 33 + lc4, b0v, b1v);
    __syncthreads();

    for (int t = 0; t < nk; t++) {
        int buf = t & 1;
        if (t + 1 < nk) {
            const float* Agn = Ag + (t + 1) * 32;
            const float* Bgn = Bg + (t + 1) * 32;
            a0v = *(const float4*)Agn;
            a1v = *(const float4*)(Agn + 16);
            b0v = *(const float4*)Bgn;
            b1v = *(const float4*)(Bgn + 16);
        }
        const uint32_t* Ab = As + buf * SMS;
        const uint32_t* Bb = Bs + buf * SMS;
#pragma unroll
        for (int kk = 0; kk < 32; kk += 8) {
            uint32_t fa0 = Ab[(wm + g) * 33 + kk + tq];
            uint32_t fa1 = Ab[(wm + g + 8) * 33 + kk + tq];
            uint32_t fa2 = Ab[(wm + g) * 33 + kk + tq + 4];
            uint32_t fa3 = Ab[(wm + g + 8) * 33 + kk + tq + 4];
#pragma unroll
            for (int j = 0; j < 4; j++) {
                uint32_t fb0 = Bb[(wn + j * 8 + g) * 33 + kk + tq];
                uint32_t fb1 = Bb[(wn + j * 8 + g) * 33 + kk + tq + 4];
                mma_tf32(acc[j], fa0, fa1, fa2, fa3, fb0, fb1);
            }
        }
        if (t + 1 < nk) {
            stage_store(As + (buf ^ 1) * SMS + lrow * 33 + lc4, a0v, a1v);
            stage_store(Bs + (buf ^ 1) * SMS + lrow * 33 + lc4, b0v, b1v);
            __syncthreads();
        }
    }
}

// ---------------------------------------------------------------------------
// Q/K/V projection GEMM: [25088x384] x [384x384]^T, scatter to head layouts
// ---------------------------------------------------------------------------
__global__ void __launch_bounds__(256) qkv_mma_kernel(
    const float* __restrict__ W, int which)
{
    __shared__ uint32_t As[2 * SMS];
    __shared__ uint32_t Bs[2 * SMS];
    const float* A = (which == 0) ? g_qt : (which == 1) ? g_kt : g_vt;

    int bm = blockIdx.x * 64, bn = blockIdx.y * 64;
    float acc[4][4] = {};
    gemm_core(A, W, Cc, Cc, Cc, bm, bn, As, Bs, acc);

    int lane = threadIdx.x & 31, warp = threadIdx.x >> 5;
    int g = lane >> 2, tq = lane & 3;
    int wm = (warp & 3) * 16, wn = (warp >> 2) * 32;
    int h = bn >> 6;

#pragma unroll
    for (int rr = 0; rr < 2; rr++) {
        int m = bm + wm + g + rr * 8;
        int b = m / Tt, t = m - b * Tt;
        int bh = b * NHh + h;
        if (which == 0) {
            float* dst = g_qp + ((size_t)bh * TP + t) * HDd;
#pragma unroll
            for (int j = 0; j < 4; j++) {
                int d = wn + j * 8 + 2 * tq;
                *(float2*)(dst + d) = make_float2(
                    acc[j][rr * 2 + 0] * SCALE_F, acc[j][rr * 2 + 1] * SCALE_F);
            }
        } else if (which == 1) {
            float* dst = g_kp + ((size_t)bh * TP + t) * HDd;
#pragma unroll
            for (int j = 0; j < 4; j++) {
                int d = wn + j * 8 + 2 * tq;
                *(float2*)(dst + d) = make_float2(
                    acc[j][rr * 2 + 0], acc[j][rr * 2 + 1]);
            }
        } else {
            float* dst = g_vT + (size_t)bh * HDd * TP + t;
#pragma unroll
            for (int j = 0; j < 4; j++) {
                int d = wn + j * 8 + 2 * tq;
                dst[(size_t)d * TP]       = acc[j][rr * 2 + 0];
                dst[(size_t)(d + 1) * TP] = acc[j][rr * 2 + 1];
            }
        }
    }
}

// ---------------------------------------------------------------------------
// S = Q K^T per (b,h): [832x64] x [832x64]^T -> [832x832]
// ---------------------------------------------------------------------------
__global__ void __launch_bounds__(256) s_mma_kernel()
{
    __shared__ uint32_t As[2 * SMS];
    __shared__ uint32_t Bs[2 * SMS];
    int bh = blockIdx.z;
    const float* A = g_qp + (size_t)bh * TP * HDd;
    const float* B = g_kp + (size_t)bh * TP * HDd;
    int bm = blockIdx.x * 64, bn = blockIdx.y * 64;
    float acc[4][4] = {};
    gemm_core(A, B, HDd, HDd, HDd, bm, bn, As, Bs, acc);

    int lane = threadIdx.x & 31, warp = threadIdx.x >> 5;
    int g = lane >> 2, tq = lane & 3;
    int wm = (warp & 3) * 16, wn = (warp >> 2) * 32;
    float* S = g_s + (size_t)bh * TP * TP;
#pragma unroll
    for (int rr = 0; rr < 2; rr++) {
        int l = bm + wm + g + rr * 8;
#pragma unroll
        for (int j = 0; j < 4; j++) {
            int t = bn + wn + j * 8 + 2 * tq;
            *(float2*)&S[(size_t)l * TP + t] =
                make_float2(acc[j][rr * 2 + 0], acc[j][rr * 2 + 1]);
        }
    }
}

// ---------------------------------------------------------------------------
// Row softmax over valid 784 cols; writes normalized probs, zeros pad cols.
// One block per valid (bh, l) row.
// ---------------------------------------------------------------------------
__global__ void __launch_bounds__(128) softmax_kernel()
{
    int rid = blockIdx.x;
    int bh = rid / Tt, l = rid - bh * Tt;
    float* row = g_s + (size_t)bh * TP * TP + (size_t)l * TP;
    int tid = threadIdx.x;

    float m = -1e30f;
    for (int c = tid; c < Tt; c += 128) m = fmaxf(m, row[c]);
#pragma unroll
    for (int o = 16; o; o >>= 1)
        m = fmaxf(m, __shfl_xor_sync(0xffffffffu, m, o));
    __shared__ float redm[4];
    if ((tid & 31) == 0) redm[tid >> 5] = m;
    __syncthreads();
    m = fmaxf(fmaxf(redm[0], redm[1]), fmaxf(redm[2], redm[3]));

    float s = 0.f;
    for (int c = tid; c < Tt; c += 128) s += __expf(row[c] - m);
#pragma unroll
    for (int o = 16; o; o >>= 1) s += __shfl_xor_sync(0xffffffffu, s, o);
    __shared__ float reds[4];
    if ((tid & 31) == 0) reds[tid >> 5] = s;
    __syncthreads();
    s = reds[0] + reds[1] + reds[2] + reds[3];
    float inv = 1.f / s;

    for (int c = tid; c < TP; c += 128)
        row[c] = (c < Tt) ? __expf(row[c] - m) * inv : 0.f;
}

// ---------------------------------------------------------------------------
// O = P V per (b,h): [832x832] x [64x832]^T -> scatter valid rows to g_o
// ---------------------------------------------------------------------------
__global__ void __launch_bounds__(256) pv_mma_kernel()
{
    __shared__ uint32_t As[2 * SMS];
    __shared__ uint32_t Bs[2 * SMS];
    int bh = blockIdx.z;
    const float* A = g_s + (size_t)bh * TP * TP;
    const float* B = g_vT + (size_t)bh * HDd * TP;
    int bm = blockIdx.x * 64, bn = 0;
    float acc[4][4] = {};
    gemm_core(A, B, TP, TP, TP, bm, bn, As, Bs, acc);

    int lane = threadIdx.x & 31, warp = threadIdx.x >> 5;
    int g = lane >> 2, tq = lane & 3;
    int wm = (warp & 3) * 16, wn = (warp >> 2) * 32;
    int b = bh / NHh, h = bh - b * NHh;
#pragma unroll
    for (int rr = 0; rr < 2; rr++) {
        int l = bm + wm + g + rr * 8;
        if (l < Tt) {
            float* dst = g_o + ((size_t)b * Tt + l) * Cc + h * HDd;
#pragma unroll
            for (int j = 0; j < 4; j++) {
                int d = wn + j * 8 + 2 * tq;
                *(float2*)(dst + d) =
                    make_float2(acc[j][rr * 2 + 0], acc[j][rr * 2 + 1]);
            }
        }
    }
}

// ---------------------------------------------------------------------------
// Output projection: [25088x384] x [384x384]^T + bias -> d_out
// ---------------------------------------------------------------------------
__global__ void __launch_bounds__(256) proj_mma_kernel(
    const float* __restrict__ W, const float* __restrict__ bias,
    float* __restrict__ out)
{
    __shared__ uint32_t As[2 * SMS];
    __shared__ uint32_t Bs[2 * SMS];
    int bm = blockIdx.x * 64, bn = blockIdx.y * 64;
    float acc[4][4] = {};
    gemm_core(g_o, W, Cc, Cc, Cc, bm, bn, As, Bs, acc);

    int lane = threadIdx.x & 31, warp = threadIdx.x >> 5;
    int g = lane >> 2, tq = lane & 3;
    int wm = (warp & 3) * 16, wn = (warp >> 2) * 32;
#pragma unroll
    for (int rr = 0; rr < 2; rr++) {
        int m = bm + wm + g + rr * 8;
#pragma unroll
        for (int j = 0; j < 4; j++) {
            int n = bn + wn + j * 8 + 2 * tq;
            float2 bb = *(const float2*)(bias + n);
            *(float2*)(out + (size_t)m * Cc + n) = make_float2(
                acc[j][rr * 2 + 0] + bb.x, acc[j][rr * 2 + 1] + bb.y);
        }
    }
}

// ---------------------------------------------------------------------------
// kernel_launch
// ---------------------------------------------------------------------------
extern "C" void kernel_launch(void* const* d_in, const int* in_sizes, int n_in,
                              void* d_out, int out_size)
{
    int base = 1;
    if (n_in >= 3 && in_sizes[1] == 1 && in_sizes[2] == 1) base = 3;

    const float* x = (const float*)d_in[0];
    const float* cw[3];
    const float* ga[3];
    const float* be[3];
    const float* me[3];
    const float* va[3];
    for (int i = 0; i < 3; i++) {
        cw[i] = (const float*)d_in[base + 5 * i + 0];
        ga[i] = (const float*)d_in[base + 5 * i + 1];
        be[i] = (const float*)d_in[base + 5 * i + 2];
        me[i] = (const float*)d_in[base + 5 * i + 3];
        va[i] = (const float*)d_in[base + 5 * i + 4];
    }
    const float* w_q    = (const float*)d_in[base + 15];
    const float* w_k    = (const float*)d_in[base + 16];
    const float* w_v    = (const float*)d_in[base + 17];
    const float* w_proj = (const float*)d_in[base + 18];
    const float* b_proj = (const float*)d_in[base + 19];
    float* out = (float*)d_out;

    convbn_kernel<<<(Mm * Cc + 255) / 256, 256>>>(
        x,
        cw[0], ga[0], be[0], me[0], va[0],
        cw[1], ga[1], be[1], me[1], va[1],
        cw[2], ga[2], be[2], me[2], va[2]);

    dim3 gg(Mm / 64, Cc / 64);
    qkv_mma_kernel<<<gg, 256>>>(w_q, 0);
    qkv_mma_kernel<<<gg, 256>>>(w_k, 1);
    qkv_mma_kernel<<<gg, 256>>>(w_v, 2);

    s_mma_kernel<<<dim3(TP / 64, TP / 64, BH), 256>>>();
    softmax_kernel<<<BH * Tt, 128>>>();
    pv_mma_kernel<<<dim3(TP / 64, 1, BH), 256>>>();

    proj_mma_kernel<<<gg, 256>>>(w_proj, b_proj, out);
}

// round 3
// speedup vs baseline: 2.9739x; 2.5879x over previous
#include <cuda_runtime.h>
#include <cuda_bf16.h>
#include <cstdint>

// Problem constants
#define Bq 32
#define Tt 784
#define Cc 384
#define NHh 6
#define HDd 64
#define Mm (Bq * Tt)          // 25088
#define TP 832                // T padded to 13*64
#define BH (Bq * NHh)         // 192
#define IMG_H 28
#define IMG_W 28
#define SCALE_F 0.05103103630798288f   // 384^-0.5

// ---------------------------------------------------------------------------
// Scratch
// ---------------------------------------------------------------------------
__device__ float g_qt[(size_t)Mm * Cc];
__device__ float g_kt[(size_t)Mm * Cc];
__device__ float g_vt[(size_t)Mm * Cc];
__device__ float g_qp[(size_t)BH * TP * HDd];  // [bh][t(pad)][d], pre-scaled
__device__ float g_kp[(size_t)BH * TP * HDd];  // [bh][t(pad)][d]
__device__ float g_vT[(size_t)BH * HDd * TP];  // [bh][d][t(pad)]
__device__ float g_o [(size_t)Mm * Cc];        // attention out [b,t,c]

// ---------------------------------------------------------------------------
// conv + BN (unchanged)
// ---------------------------------------------------------------------------
__global__ void __launch_bounds__(256) convbn_kernel(
    const float* __restrict__ x,
    const float* __restrict__ cwq, const float* __restrict__ gq,
    const float* __restrict__ beq, const float* __restrict__ meq,
    const float* __restrict__ vaq,
    const float* __restrict__ cwk, const float* __restrict__ gk,
    const float* __restrict__ bek, const float* __restrict__ mek,
    const float* __restrict__ vak,
    const float* __restrict__ cwv, const float* __restrict__ gv,
    const float* __restrict__ bev, const float* __restrict__ mev,
    const float* __restrict__ vav)
{
    int idx = blockIdx.x * 256 + threadIdx.x;
    if (idx >= Mm * Cc) return;
    int c  = idx % Cc;
    int bt = idx / Cc;
    int t  = bt % Tt;
    int b  = bt / Tt;
    int y  = t / IMG_W;
    int xp = t % IMG_W;

    float vals[9];
#pragma unroll
    for (int dy = 0; dy < 3; dy++) {
#pragma unroll
        for (int dx = 0; dx < 3; dx++) {
            int yy = y + dy - 1, xx = xp + dx - 1;
            bool in = (yy >= 0) && (yy < IMG_H) && (xx >= 0) && (xx < IMG_W);
            vals[dy * 3 + dx] =
                in ? x[((size_t)b * Tt + yy * IMG_W + xx) * Cc + c] : 0.f;
        }
    }
    {
        float acc = 0.f;
#pragma unroll
        for (int i = 0; i < 9; i++) acc += vals[i] * cwq[c * 9 + i];
        float inv = gq[c] * rsqrtf(vaq[c] + 1e-5f);
        g_qt[idx] = acc * inv + (beq[c] - meq[c] * inv);
    }
    {
        float acc = 0.f;
#pragma unroll
        for (int i = 0; i < 9; i++) acc += vals[i] * cwk[c * 9 + i];
        float inv = gk[c] * rsqrtf(vak[c] + 1e-5f);
        g_kt[idx] = acc * inv + (bek[c] - mek[c] * inv);
    }
    {
        float acc = 0.f;
#pragma unroll
        for (int i = 0; i < 9; i++) acc += vals[i] * cwv[c * 9 + i];
        float inv = gv[c] * rsqrtf(vav[c] + 1e-5f);
        g_vt[idx] = acc * inv + (bev[c] - mev[c] * inv);
    }
}

// ---------------------------------------------------------------------------
// tf32 mma helpers
// ---------------------------------------------------------------------------
__device__ __forceinline__ uint32_t f2tf32(float f) {
    uint32_t u;
    asm("cvt.rna.tf32.f32 %0, %1;" : "=r"(u) : "f"(f));
    return u;
}

__device__ __forceinline__ void mma_tf32(float c[4],
    uint32_t a0, uint32_t a1, uint32_t a2, uint32_t a3,
    uint32_t b0, uint32_t b1)
{
    asm volatile(
        "mma.sync.aligned.m16n8k8.row.col.f32.tf32.tf32.f32 "
        "{%0,%1,%2,%3}, {%4,%5,%6,%7}, {%8,%9}, {%0,%1,%2,%3};"
        : "+f"(c[0]), "+f"(c[1]), "+f"(c[2]), "+f"(c[3])
        : "r"(a0), "r"(a1), "r"(a2), "r"(a3), "r"(b0), "r"(b1));
}

// permuted k position within a 16-group: pairs (k, k+4) adjacent
__device__ __forceinline__ int pos16(int k) {
    return (k & 8) | ((k & 3) << 1) | ((k & 4) >> 2);
}

// store 8 consecutive k values (lo: k=kb..kb+3, hi: k=kb+4..kb+7) permuted
__device__ __forceinline__ void store_perm8(uint32_t* dst_row, int kb,
                                            float4 lo, float4 hi) {
    uint2* d = (uint2*)(dst_row + kb);
    d[0] = make_uint2(f2tf32(lo.x), f2tf32(hi.x));
    d[1] = make_uint2(f2tf32(lo.y), f2tf32(hi.y));
    d[2] = make_uint2(f2tf32(lo.z), f2tf32(hi.z));
    d[3] = make_uint2(f2tf32(lo.w), f2tf32(hi.w));
}

// ---------------------------------------------------------------------------
// GEMM core: 128x128 tile, NT (A[M,K] row, B[N,K] row), K mult of 16.
// 256 threads, 8 warps = 2(m) x 4(n); warp tile 64x32. BK=16 double-buffered.
// acc[ms][j][4]: rows wm+ms*16+g+{0,8}, cols wn+j*8+{2tq,2tq+1}
// ---------------------------------------------------------------------------
#define STRG 24
#define GEMM_SM (128 * STRG)

__device__ __forceinline__ void gemm128_core(
    const float* __restrict__ A, const float* __restrict__ B,
    int lda, int ldb, int K, int bm, int bn,
    uint32_t* As, uint32_t* Bs, float acc[4][4][4])
{
    const int tid  = threadIdx.x;
    const int lane = tid & 31;
    const int warp = tid >> 5;
    const int g    = lane >> 2;
    const int tq   = lane & 3;
    const int wm   = (warp & 1) * 64;
    const int wn   = (warp >> 1) * 32;
    const int lrow = tid >> 1;          // 0..127
    const int lkb  = (tid & 1) * 8;     // 0 or 8

    const float* Ag = A + (size_t)(bm + lrow) * lda + lkb;
    const float* Bg = B + (size_t)(bn + lrow) * ldb + lkb;

    float4 pa0 = *(const float4*)Ag;
    float4 pa1 = *(const float4*)(Ag + 4);
    float4 pb0 = *(const float4*)Bg;
    float4 pb1 = *(const float4*)(Bg + 4);

    const int nslab = K >> 4;
    for (int s = 0; s < nslab; s++) {
        uint32_t* Ab = As + (s & 1) * GEMM_SM;
        uint32_t* Bb = Bs + (s & 1) * GEMM_SM;
        store_perm8(Ab + lrow * STRG, lkb, pa0, pa1);
        store_perm8(Bb + lrow * STRG, lkb, pb0, pb1);
        if (s + 1 < nslab) {
            const float* Agn = Ag + (s + 1) * 16;
            const float* Bgn = Bg + (s + 1) * 16;
            pa0 = *(const float4*)Agn;
            pa1 = *(const float4*)(Agn + 4);
            pb0 = *(const float4*)Bgn;
            pb1 = *(const float4*)(Bgn + 4);
        }
        __syncthreads();
#pragma unroll
        for (int kk = 0; kk < 16; kk += 8) {
            uint32_t a[4][4];
#pragma unroll
            for (int ms = 0; ms < 4; ms++) {
                uint2 lo = *(const uint2*)&Ab[(wm + ms * 16 + g) * STRG + kk + 2 * tq];
                uint2 hi = *(const uint2*)&Ab[(wm + ms * 16 + g + 8) * STRG + kk + 2 * tq];
                a[ms][0] = lo.x; a[ms][2] = lo.y;
                a[ms][1] = hi.x; a[ms][3] = hi.y;
            }
#pragma unroll
            for (int j = 0; j < 4; j++) {
                uint2 bv = *(const uint2*)&Bb[(wn + j * 8 + g) * STRG + kk + 2 * tq];
#pragma unroll
                for (int ms = 0; ms < 4; ms++)
                    mma_tf32(acc[ms][j], a[ms][0], a[ms][1], a[ms][2], a[ms][3],
                             bv.x, bv.y);
            }
        }
        __syncthreads();
    }
}

// ---------------------------------------------------------------------------
// Q/K/V projection
// ---------------------------------------------------------------------------
__global__ void __launch_bounds__(256) qkv_mma_kernel(
    const float* __restrict__ W, int which)
{
    __shared__ uint32_t As[2 * GEMM_SM];
    __shared__ uint32_t Bs[2 * GEMM_SM];
    const float* A = (which == 0) ? g_qt : (which == 1) ? g_kt : g_vt;

    int bm = blockIdx.x * 128, bn = blockIdx.y * 128;
    float acc[4][4][4] = {};
    gemm128_core(A, W, Cc, Cc, Cc, bm, bn, As, Bs, acc);

    int lane = threadIdx.x & 31, warp = threadIdx.x >> 5;
    int g = lane >> 2, tq = lane & 3;
    int wm = (warp & 1) * 64, wn = (warp >> 1) * 32;
    int h = (bn + wn) >> 6;        // fixed per warp (wn multiple of 32)

#pragma unroll
    for (int ms = 0; ms < 4; ms++) {
#pragma unroll
        for (int rr = 0; rr < 2; rr++) {
            int m = bm + wm + ms * 16 + g + rr * 8;
            int b = m / Tt, t = m - b * Tt;
            int bh = b * NHh + h;
            if (which == 0) {
                float* dst = g_qp + ((size_t)bh * TP + t) * HDd;
#pragma unroll
                for (int j = 0; j < 4; j++) {
                    int d = (bn + wn + j * 8 + 2 * tq) & 63;
                    *(float2*)(dst + d) = make_float2(
                        acc[ms][j][rr * 2 + 0] * SCALE_F,
                        acc[ms][j][rr * 2 + 1] * SCALE_F);
                }
            } else if (which == 1) {
                float* dst = g_kp + ((size_t)bh * TP + t) * HDd;
#pragma unroll
                for (int j = 0; j < 4; j++) {
                    int d = (bn + wn + j * 8 + 2 * tq) & 63;
                    *(float2*)(dst + d) = make_float2(
                        acc[ms][j][rr * 2 + 0], acc[ms][j][rr * 2 + 1]);
                }
            } else {
                float* dst = g_vT + (size_t)bh * HDd * TP + t;
#pragma unroll
                for (int j = 0; j < 4; j++) {
                    int d = (bn + wn + j * 8 + 2 * tq) & 63;
                    dst[(size_t)d * TP]       = acc[ms][j][rr * 2 + 0];
                    dst[(size_t)(d + 1) * TP] = acc[ms][j][rr * 2 + 1];
                }
            }
        }
    }
}

// ---------------------------------------------------------------------------
// Output projection
// ---------------------------------------------------------------------------
__global__ void __launch_bounds__(256) proj_mma_kernel(
    const float* __restrict__ W, const float* __restrict__ bias,
    float* __restrict__ out)
{
    __shared__ uint32_t As[2 * GEMM_SM];
    __shared__ uint32_t Bs[2 * GEMM_SM];
    int bm = blockIdx.x * 128, bn = blockIdx.y * 128;
    float acc[4][4][4] = {};
    gemm128_core(g_o, W, Cc, Cc, Cc, bm, bn, As, Bs, acc);

    int lane = threadIdx.x & 31, warp = threadIdx.x >> 5;
    int g = lane >> 2, tq = lane & 3;
    int wm = (warp & 1) * 64, wn = (warp >> 1) * 32;
#pragma unroll
    for (int ms = 0; ms < 4; ms++) {
#pragma unroll
        for (int rr = 0; rr < 2; rr++) {
            int m = bm + wm + ms * 16 + g + rr * 8;
#pragma unroll
            for (int j = 0; j < 4; j++) {
                int n = bn + wn + j * 8 + 2 * tq;
                float2 bb = *(const float2*)(bias + n);
                *(float2*)(out + (size_t)m * Cc + n) = make_float2(
                    acc[ms][j][rr * 2 + 0] + bb.x,
                    acc[ms][j][rr * 2 + 1] + bb.y);
            }
        }
    }
}

// ---------------------------------------------------------------------------
// Flash attention: block = (bh, 64 q rows), 128 threads (4 warps x 16 rows).
// Q fragments in registers; K / V^T tiles staged tf32-permuted in smem;
// P overwrites the K buffer. Online softmax in accumulators.
// ---------------------------------------------------------------------------
#define STRF 72

__global__ void __launch_bounds__(128) flash_kernel()
{
    __shared__ uint32_t Ks[64 * STRF];   // K tile, then P tile
    __shared__ uint32_t Vs[64 * STRF];   // V^T tile

    int bh = blockIdx.y;
    int q0 = blockIdx.x * 64;
    int tid = threadIdx.x, lane = tid & 31, warp = tid >> 5;
    int g = lane >> 2, tq = lane & 3;

    const float* Qb = g_qp + (size_t)bh * TP * HDd;
    const float* Kb = g_kp + (size_t)bh * TP * HDd;
    const float* Vb = g_vT + (size_t)bh * HDd * TP;

    // Q fragments (rows q0+warp*16+g, +8), all 8 kk steps, in registers
    uint32_t qf[8][4];
    {
        const float* r0 = Qb + (size_t)(q0 + warp * 16 + g) * HDd;
        const float* r1 = r0 + 8 * HDd;
#pragma unroll
        for (int k8 = 0; k8 < 8; k8++) {
            qf[k8][0] = f2tf32(r0[k8 * 8 + tq]);
            qf[k8][2] = f2tf32(r0[k8 * 8 + tq + 4]);
            qf[k8][1] = f2tf32(r1[k8 * 8 + tq]);
            qf[k8][3] = f2tf32(r1[k8 * 8 + tq + 4]);
        }
    }

    float oacc[8][4];
#pragma unroll
    for (int j = 0; j < 8; j++)
#pragma unroll
        for (int i = 0; i < 4; i++) oacc[j][i] = 0.f;
    float m0 = -1e30f, m1 = -1e30f, l0 = 0.f, l1 = 0.f;

    const int lrow = tid >> 1;            // 0..63
    const int lh   = (tid & 1) * 32;      // column half

    for (int ct = 0; ct < 13; ct++) {
        int t0 = ct * 64;
        __syncthreads();   // previous chunk fully consumed
        // stage K tile: rows = t-local, k-dim = d (permuted)
        {
            const float* src = Kb + (size_t)(t0 + lrow) * HDd + lh;
            uint32_t* dst = Ks + lrow * STRF;
#pragma unroll
            for (int c8 = 0; c8 < 4; c8++) {
                float4 lo = *(const float4*)(src + c8 * 8);
                float4 hi = *(const float4*)(src + c8 * 8 + 4);
                store_perm8(dst, lh + c8 * 8, lo, hi);
            }
            const float* sv = Vb + (size_t)lrow * TP + t0 + lh;
            uint32_t* dv = Vs + lrow * STRF;
#pragma unroll
            for (int c8 = 0; c8 < 4; c8++) {
                float4 lo = *(const float4*)(sv + c8 * 8);
                float4 hi = *(const float4*)(sv + c8 * 8 + 4);
                store_perm8(dv, lh + c8 * 8, lo, hi);
            }
        }
        __syncthreads();

        // S = Q K^T  (warp rows 16 x 64 keys)
        float sacc[8][4];
#pragma unroll
        for (int j = 0; j < 8; j++)
#pragma unroll
            for (int i = 0; i < 4; i++) sacc[j][i] = 0.f;
#pragma unroll
        for (int kk = 0; kk < 64; kk += 8) {
#pragma unroll
            for (int j = 0; j < 8; j++) {
                uint2 bv = *(const uint2*)&Ks[(j * 8 + g) * STRF + kk + 2 * tq];
                mma_tf32(sacc[j], qf[kk >> 3][0], qf[kk >> 3][1],
                         qf[kk >> 3][2], qf[kk >> 3][3], bv.x, bv.y);
            }
        }

        // mask invalid keys (only last chunk: cols >= 16 invalid)
        if (ct == 12) {
#pragma unroll
            for (int j = 2; j < 8; j++)
#pragma unroll
                for (int i = 0; i < 4; i++) sacc[j][i] = -1e30f;
        }

        // online softmax
        float t0m = -1e30f, t1m = -1e30f;
#pragma unroll
        for (int j = 0; j < 8; j++) {
            t0m = fmaxf(t0m, fmaxf(sacc[j][0], sacc[j][1]));
            t1m = fmaxf(t1m, fmaxf(sacc[j][2], sacc[j][3]));
        }
        t0m = fmaxf(t0m, __shfl_xor_sync(0xffffffffu, t0m, 1));
        t0m = fmaxf(t0m, __shfl_xor_sync(0xffffffffu, t0m, 2));
        t1m = fmaxf(t1m, __shfl_xor_sync(0xffffffffu, t1m, 1));
        t1m = fmaxf(t1m, __shfl_xor_sync(0xffffffffu, t1m, 2));
        float mn0 = fmaxf(m0, t0m), mn1 = fmaxf(m1, t1m);
        float sc0 = __expf(m0 - mn0), sc1 = __expf(m1 - mn1);
        m0 = mn0; m1 = mn1;
        l0 *= sc0; l1 *= sc1;
        float ps0 = 0.f, ps1 = 0.f;
#pragma unroll
        for (int j = 0; j < 8; j++) {
            oacc[j][0] *= sc0; oacc[j][1] *= sc0;
            oacc[j][2] *= sc1; oacc[j][3] *= sc1;
            sacc[j][0] = __expf(sacc[j][0] - mn0);
            sacc[j][1] = __expf(sacc[j][1] - mn0);
            sacc[j][2] = __expf(sacc[j][2] - mn1);
            sacc[j][3] = __expf(sacc[j][3] - mn1);
            ps0 += sacc[j][0] + sacc[j][1];
            ps1 += sacc[j][2] + sacc[j][3];
        }
        l0 += ps0; l1 += ps1;

        __syncthreads();   // all warps done reading Ks (S stage)

        // write P over Ks (own warp rows only)
        {
            uint32_t* pr0 = Ks + (warp * 16 + g) * STRF;
            uint32_t* pr1 = pr0 + 8 * STRF;
#pragma unroll
            for (int j = 0; j < 8; j++) {
                int c0 = j * 8 + 2 * tq;
                int c1 = c0 + 1;
                int p0 = (c0 & 48) | pos16(c0 & 15);
                int p1 = (c1 & 48) | pos16(c1 & 15);
                pr0[p0] = f2tf32(sacc[j][0]);
                pr0[p1] = f2tf32(sacc[j][1]);
                pr1[p0] = f2tf32(sacc[j][2]);
                pr1[p1] = f2tf32(sacc[j][3]);
            }
        }
        __syncwarp();

        // O += P V   (A = own P rows, B = V^T rows (d), k = t-local)
#pragma unroll
        for (int kk = 0; kk < 64; kk += 8) {
            uint2 alo = *(const uint2*)&Ks[(warp * 16 + g) * STRF + kk + 2 * tq];
            uint2 ahi = *(const uint2*)&Ks[(warp * 16 + g + 8) * STRF + kk + 2 * tq];
#pragma unroll
            for (int j = 0; j < 8; j++) {
                uint2 bv = *(const uint2*)&Vs[(j * 8 + g) * STRF + kk + 2 * tq];
                mma_tf32(oacc[j], alo.x, ahi.x, alo.y, ahi.y, bv.x, bv.y);
            }
        }
    }

    // finalize
    l0 += __shfl_xor_sync(0xffffffffu, l0, 1);
    l0 += __shfl_xor_sync(0xffffffffu, l0, 2);
    l1 += __shfl_xor_sync(0xffffffffu, l1, 1);
    l1 += __shfl_xor_sync(0xffffffffu, l1, 2);
    float inv0 = 1.f / l0, inv1 = 1.f / l1;

    int b = bh / NHh, h = bh - (bh / NHh) * NHh;
    int r0g = q0 + warp * 16 + g, r1g = r0g + 8;
    if (r0g < Tt) {
        float* dst = g_o + ((size_t)b * Tt + r0g) * Cc + h * HDd;
#pragma unroll
        for (int j = 0; j < 8; j++)
            *(float2*)(dst + j * 8 + 2 * tq) =
                make_float2(oacc[j][0] * inv0, oacc[j][1] * inv0);
    }
    if (r1g < Tt) {
        float* dst = g_o + ((size_t)b * Tt + r1g) * Cc + h * HDd;
#pragma unroll
        for (int j = 0; j < 8; j++)
            *(float2*)(dst + j * 8 + 2 * tq) =
                make_float2(oacc[j][2] * inv1, oacc[j][3] * inv1);
    }
}

// ---------------------------------------------------------------------------
// kernel_launch
// ---------------------------------------------------------------------------
extern "C" void kernel_launch(void* const* d_in, const int* in_sizes, int n_in,
                              void* d_out, int out_size)
{
    int base = 1;
    if (n_in >= 3 && in_sizes[1] == 1 && in_sizes[2] == 1) base = 3;

    const float* x = (const float*)d_in[0];
    const float* cw[3];
    const float* ga[3];
    const float* be[3];
    const float* me[3];
    const float* va[3];
    for (int i = 0; i < 3; i++) {
        cw[i] = (const float*)d_in[base + 5 * i + 0];
        ga[i] = (const float*)d_in[base + 5 * i + 1];
        be[i] = (const float*)d_in[base + 5 * i + 2];
        me[i] = (const float*)d_in[base + 5 * i + 3];
        va[i] = (const float*)d_in[base + 5 * i + 4];
    }
    const float* w_q    = (const float*)d_in[base + 15];
    const float* w_k    = (const float*)d_in[base + 16];
    const float* w_v    = (const float*)d_in[base + 17];
    const float* w_proj = (const float*)d_in[base + 18];
    const float* b_proj = (const float*)d_in[base + 19];
    float* out = (float*)d_out;

    convbn_kernel<<<(Mm * Cc + 255) / 256, 256>>>(
        x,
        cw[0], ga[0], be[0], me[0], va[0],
        cw[1], ga[1], be[1], me[1], va[1],
        cw[2], ga[2], be[2], me[2], va[2]);

    dim3 gg(Mm / 128, Cc / 128);
    qkv_mma_kernel<<<gg, 256>>>(w_q, 0);
    qkv_mma_kernel<<<gg, 256>>>(w_k, 1);
    qkv_mma_kernel<<<gg, 256>>>(w_v, 2);

    flash_kernel<<<dim3(13, BH), 128>>>();

    proj_mma_kernel<<<gg, 256>>>(w_proj, b_proj, out);
}

// round 5
// speedup vs baseline: 3.0655x; 1.0308x over previous
#include <cuda_runtime.h>
#include <cuda_bf16.h>
#include <cstdint>

// Problem constants
#define Bq 32
#define Tt 784
#define Cc 384
#define NHh 6
#define HDd 64
#define Mm (Bq * Tt)          // 25088
#define TP 832                // T padded to 13*64
#define BH (Bq * NHh)         // 192
#define IMG_H 28
#define IMG_W 28
#define SCALE_F 0.05103103630798288f   // 384^-0.5

// ---------------------------------------------------------------------------
// Scratch
// ---------------------------------------------------------------------------
__device__ float g_qt[(size_t)Mm * Cc];
__device__ float g_kt[(size_t)Mm * Cc];
__device__ float g_vt[(size_t)Mm * Cc];
__device__ float g_qp[(size_t)BH * TP * HDd];  // [bh][t][d] plain, pre-scaled
__device__ float g_kp[(size_t)BH * TP * HDd];  // [bh][t][d-permuted] tf32 bits
__device__ float g_vT[(size_t)BH * HDd * TP];  // [bh][d][t-permuted] tf32 bits
__device__ float g_o [(size_t)Mm * Cc];        // attention out [b,t,c]

// ---------------------------------------------------------------------------
// conv + BN
// ---------------------------------------------------------------------------
__global__ void __launch_bounds__(256) convbn_kernel(
    const float* __restrict__ x,
    const float* __restrict__ cwq, const float* __restrict__ gq,
    const float* __restrict__ beq, const float* __restrict__ meq,
    const float* __restrict__ vaq,
    const float* __restrict__ cwk, const float* __restrict__ gk,
    const float* __restrict__ bek, const float* __restrict__ mek,
    const float* __restrict__ vak,
    const float* __restrict__ cwv, const float* __restrict__ gv,
    const float* __restrict__ bev, const float* __restrict__ mev,
    const float* __restrict__ vav)
{
    int idx = blockIdx.x * 256 + threadIdx.x;
    if (idx >= Mm * Cc) return;
    int c  = idx % Cc;
    int bt = idx / Cc;
    int t  = bt % Tt;
    int b  = bt / Tt;
    int y  = t / IMG_W;
    int xp = t % IMG_W;

    float vals[9];
#pragma unroll
    for (int dy = 0; dy < 3; dy++) {
#pragma unroll
        for (int dx = 0; dx < 3; dx++) {
            int yy = y + dy - 1, xx = xp + dx - 1;
            bool in = (yy >= 0) && (yy < IMG_H) && (xx >= 0) && (xx < IMG_W);
            vals[dy * 3 + dx] =
                in ? x[((size_t)b * Tt + yy * IMG_W + xx) * Cc + c] : 0.f;
        }
    }
    {
        float acc = 0.f;
#pragma unroll
        for (int i = 0; i < 9; i++) acc += vals[i] * cwq[c * 9 + i];
        float inv = gq[c] * rsqrtf(vaq[c] + 1e-5f);
        g_qt[idx] = acc * inv + (beq[c] - meq[c] * inv);
    }
    {
        float acc = 0.f;
#pragma unroll
        for (int i = 0; i < 9; i++) acc += vals[i] * cwk[c * 9 + i];
        float inv = gk[c] * rsqrtf(vak[c] + 1e-5f);
        g_kt[idx] = acc * inv + (bek[c] - mek[c] * inv);
    }
    {
        float acc = 0.f;
#pragma unroll
        for (int i = 0; i < 9; i++) acc += vals[i] * cwv[c * 9 + i];
        float inv = gv[c] * rsqrtf(vav[c] + 1e-5f);
        g_vt[idx] = acc * inv + (bev[c] - mev[c] * inv);
    }
}

// ---------------------------------------------------------------------------
// tf32 mma helpers
// ---------------------------------------------------------------------------
__device__ __forceinline__ uint32_t f2tf32(float f) {
    uint32_t u;
    asm("cvt.rna.tf32.f32 %0, %1;" : "=r"(u) : "f"(f));
    return u;
}

__device__ __forceinline__ void mma_tf32(float c[4],
    uint32_t a0, uint32_t a1, uint32_t a2, uint32_t a3,
    uint32_t b0, uint32_t b1)
{
    asm volatile(
        "mma.sync.aligned.m16n8k8.row.col.f32.tf32.tf32.f32 "
        "{%0,%1,%2,%3}, {%4,%5,%6,%7}, {%8,%9}, {%0,%1,%2,%3};"
        : "+f"(c[0]), "+f"(c[1]), "+f"(c[2]), "+f"(c[3])
        : "r"(a0), "r"(a1), "r"(a2), "r"(a3), "r"(b0), "r"(b1));
}

// permuted k position within a 16-group: pairs (k, k+4) adjacent
__device__ __forceinline__ int pos16(int k) {
    return (k & 8) | ((k & 3) << 1) | ((k & 4) >> 2);
}
// row permutation within an 8-group (n-dim): source key for smem row r
__device__ __forceinline__ int perm8(int n) {
    return (n >> 1) + ((n & 1) << 2);
}

__device__ __forceinline__ void store_perm8(uint32_t* dst_row, int kb,
                                            float4 lo, float4 hi) {
    uint2* d = (uint2*)(dst_row + kb);
    d[0] = make_uint2(f2tf32(lo.x), f2tf32(hi.x));
    d[1] = make_uint2(f2tf32(lo.y), f2tf32(hi.y));
    d[2] = make_uint2(f2tf32(lo.z), f2tf32(hi.z));
    d[3] = make_uint2(f2tf32(lo.w), f2tf32(hi.w));
}

// ---------------------------------------------------------------------------
// GEMM core: 128x128 tile, NT, K mult of 16. 256 threads.
// ---------------------------------------------------------------------------
#define STRG 24
#define GEMM_SM (128 * STRG)

__device__ __forceinline__ void gemm128_core(
    const float* __restrict__ A, const float* __restrict__ B,
    int lda, int ldb, int K, int bm, int bn,
    uint32_t* As, uint32_t* Bs, float acc[4][4][4])
{
    const int tid  = threadIdx.x;
    const int lane = tid & 31;
    const int warp = tid >> 5;
    const int g    = lane >> 2;
    const int tq   = lane & 3;
    const int wm   = (warp & 1) * 64;
    const int wn   = (warp >> 1) * 32;
    const int lrow = tid >> 1;
    const int lkb  = (tid & 1) * 8;

    const float* Ag = A + (size_t)(bm + lrow) * lda + lkb;
    const float* Bg = B + (size_t)(bn + lrow) * ldb + lkb;

    float4 pa0 = *(const float4*)Ag;
    float4 pa1 = *(const float4*)(Ag + 4);
    float4 pb0 = *(const float4*)Bg;
    float4 pb1 = *(const float4*)(Bg + 4);

    const int nslab = K >> 4;
    for (int s = 0; s < nslab; s++) {
        uint32_t* Ab = As + (s & 1) * GEMM_SM;
        uint32_t* Bb = Bs + (s & 1) * GEMM_SM;
        store_perm8(Ab + lrow * STRG, lkb, pa0, pa1);
        store_perm8(Bb + lrow * STRG, lkb, pb0, pb1);
        if (s + 1 < nslab) {
            const float* Agn = Ag + (s + 1) * 16;
            const float* Bgn = Bg + (s + 1) * 16;
            pa0 = *(const float4*)Agn;
            pa1 = *(const float4*)(Agn + 4);
            pb0 = *(const float4*)Bgn;
            pb1 = *(const float4*)(Bgn + 4);
        }
        __syncthreads();
#pragma unroll
        for (int kk = 0; kk < 16; kk += 8) {
            uint32_t a[4][4];
#pragma unroll
            for (int ms = 0; ms < 4; ms++) {
                uint2 lo = *(const uint2*)&Ab[(wm + ms * 16 + g) * STRG + kk + 2 * tq];
                uint2 hi = *(const uint2*)&Ab[(wm + ms * 16 + g + 8) * STRG + kk + 2 * tq];
                a[ms][0] = lo.x; a[ms][2] = lo.y;
                a[ms][1] = hi.x; a[ms][3] = hi.y;
            }
#pragma unroll
            for (int j = 0; j < 4; j++) {
                uint2 bv = *(const uint2*)&Bb[(wn + j * 8 + g) * STRG + kk + 2 * tq];
#pragma unroll
                for (int ms = 0; ms < 4; ms++)
                    mma_tf32(acc[ms][j], a[ms][0], a[ms][1], a[ms][2], a[ms][3],
                             bv.x, bv.y);
            }
        }
        __syncthreads();
    }
}

// ---------------------------------------------------------------------------
// Q/K/V projection; K and V written pre-permuted + tf32-rounded
// ---------------------------------------------------------------------------
__global__ void __launch_bounds__(256) qkv_mma_kernel(
    const float* __restrict__ W, int which)
{
    __shared__ uint32_t As[2 * GEMM_SM];
    __shared__ uint32_t Bs[2 * GEMM_SM];
    const float* A = (which == 0) ? g_qt : (which == 1) ? g_kt : g_vt;

    int bm = blockIdx.x * 128, bn = blockIdx.y * 128;
    float acc[4][4][4] = {};
    gemm128_core(A, W, Cc, Cc, Cc, bm, bn, As, Bs, acc);

    int lane = threadIdx.x & 31, warp = threadIdx.x >> 5;
    int g = lane >> 2, tq = lane & 3;
    int wm = (warp & 1) * 64, wn = (warp >> 1) * 32;
    int h = (bn + wn) >> 6;

#pragma unroll
    for (int ms = 0; ms < 4; ms++) {
#pragma unroll
        for (int rr = 0; rr < 2; rr++) {
            int m = bm + wm + ms * 16 + g + rr * 8;
            int b = m / Tt, t = m - b * Tt;
            int bh = b * NHh + h;
            if (which == 0) {
                float* dst = g_qp + ((size_t)bh * TP + t) * HDd;
#pragma unroll
                for (int j = 0; j < 4; j++) {
                    int d = (bn + wn + j * 8 + 2 * tq) & 63;
                    *(float2*)(dst + d) = make_float2(
                        acc[ms][j][rr * 2 + 0] * SCALE_F,
                        acc[ms][j][rr * 2 + 1] * SCALE_F);
                }
            } else if (which == 1) {
                float* dst = g_kp + ((size_t)bh * TP + t) * HDd;
#pragma unroll
                for (int j = 0; j < 4; j++) {
                    int c0 = (bn + wn + j * 8 + 2 * tq) & 63;
                    int p0 = (c0 & 48) | pos16(c0 & 15);
                    int p1 = (c0 & 48) | pos16((c0 + 1) & 15);
                    dst[p0] = __uint_as_float(f2tf32(acc[ms][j][rr * 2 + 0]));
                    dst[p1] = __uint_as_float(f2tf32(acc[ms][j][rr * 2 + 1]));
                }
            } else {
                int tp = (t & ~15) | pos16(t & 15);
                float* dst = g_vT + (size_t)bh * HDd * TP + tp;
#pragma unroll
                for (int j = 0; j < 4; j++) {
                    int d = (bn + wn + j * 8 + 2 * tq) & 63;
                    dst[(size_t)d * TP] =
                        __uint_as_float(f2tf32(acc[ms][j][rr * 2 + 0]));
                    dst[(size_t)(d + 1) * TP] =
                        __uint_as_float(f2tf32(acc[ms][j][rr * 2 + 1]));
                }
            }
        }
    }
}

// ---------------------------------------------------------------------------
// Output projection
// ---------------------------------------------------------------------------
__global__ void __launch_bounds__(256) proj_mma_kernel(
    const float* __restrict__ W, const float* __restrict__ bias,
    float* __restrict__ out)
{
    __shared__ uint32_t As[2 * GEMM_SM];
    __shared__ uint32_t Bs[2 * GEMM_SM];
    int bm = blockIdx.x * 128, bn = blockIdx.y * 128;
    float acc[4][4][4] = {};
    gemm128_core(g_o, W, Cc, Cc, Cc, bm, bn, As, Bs, acc);

    int lane = threadIdx.x & 31, warp = threadIdx.x >> 5;
    int g = lane >> 2, tq = lane & 3;
    int wm = (warp & 1) * 64, wn = (warp >> 1) * 32;
#pragma unroll
    for (int ms = 0; ms < 4; ms++) {
#pragma unroll
        for (int rr = 0; rr < 2; rr++) {
            int m = bm + wm + ms * 16 + g + rr * 8;
#pragma unroll
            for (int j = 0; j < 4; j++) {
                int n = bn + wn + j * 8 + 2 * tq;
                float2 bb = *(const float2*)(bias + n);
                *(float2*)(out + (size_t)m * Cc + n) = make_float2(
                    acc[ms][j][rr * 2 + 0] + bb.x,
                    acc[ms][j][rr * 2 + 1] + bb.y);
            }
        }
    }
}

// ---------------------------------------------------------------------------
// Flash attention. Block = (bh, 64 q rows), 128 threads.
// K/V tiles are pure uint4 copies (already tf32+permuted in global).
// K tile rows permuted so S accumulator fragment feeds PV directly:
//   sacc[j][0]=(row g,   key j*8+tq)   sacc[j][1]=(row g,   key j*8+tq+4)
//   sacc[j][2]=(row g+8, key j*8+tq)   sacc[j][3]=(row g+8, key j*8+tq+4)
// ---------------------------------------------------------------------------
#define STRF 72

__global__ void __launch_bounds__(128) flash_kernel()
{
    __shared__ uint32_t Ks[64 * STRF];
    __shared__ uint32_t Vs[64 * STRF];

    int bh = blockIdx.y;
    int q0 = blockIdx.x * 64;
    int tid = threadIdx.x, lane = tid & 31, warp = tid >> 5;
    int g = lane >> 2, tq = lane & 3;

    const float* Qb = g_qp + (size_t)bh * TP * HDd;
    const float* Kb = g_kp + (size_t)bh * TP * HDd;
    const float* Vb = g_vT + (size_t)bh * HDd * TP;

    // Q fragments in registers (plain layout, logical d indexing)
    uint32_t qf[8][4];
    {
        const float* r0 = Qb + (size_t)(q0 + warp * 16 + g) * HDd;
        const float* r1 = r0 + 8 * HDd;
#pragma unroll
        for (int k8 = 0; k8 < 8; k8++) {
            qf[k8][0] = f2tf32(r0[k8 * 8 + tq]);
            qf[k8][2] = f2tf32(r0[k8 * 8 + tq + 4]);
            qf[k8][1] = f2tf32(r1[k8 * 8 + tq]);
            qf[k8][3] = f2tf32(r1[k8 * 8 + tq + 4]);
        }
    }

    float oacc[8][4];
#pragma unroll
    for (int j = 0; j < 8; j++)
#pragma unroll
        for (int i = 0; i < 4; i++) oacc[j][i] = 0.f;
    float m0 = -1e30f, m1 = -1e30f, l0 = 0.f, l1 = 0.f;

    const int lrow = tid >> 1;            // 0..63
    const int lh   = (tid & 1) * 32;      // column half (words)
    const int krow = (lrow & ~7) | perm8(lrow & 7);  // source key for Ks row

    for (int ct = 0; ct < 13; ct++) {
        int t0 = ct * 64;
        __syncthreads();
        // stage K (row-permuted) and V^T — pure copies
        {
            const uint4* ks = (const uint4*)(Kb + (size_t)(t0 + krow) * HDd + lh);
            uint4* kd = (uint4*)(Ks + lrow * STRF + lh);
            const uint4* vs = (const uint4*)(Vb + (size_t)lrow * TP + t0 + lh);
            uint4* vd = (uint4*)(Vs + lrow * STRF + lh);
#pragma unroll
            for (int i = 0; i < 8; i++) {
                kd[i] = ks[i];
                vd[i] = vs[i];
            }
        }
        __syncthreads();

        // S = Q K^T
        float sacc[8][4];
#pragma unroll
        for (int j = 0; j < 8; j++)
#pragma unroll
            for (int i = 0; i < 4; i++) sacc[j][i] = 0.f;
#pragma unroll
        for (int kk = 0; kk < 64; kk += 8) {
#pragma unroll
            for (int j = 0; j < 8; j++) {
                uint2 bv = *(const uint2*)&Ks[(j * 8 + g) * STRF + kk + 2 * tq];
                mma_tf32(sacc[j], qf[kk >> 3][0], qf[kk >> 3][1],
                         qf[kk >> 3][2], qf[kk >> 3][3], bv.x, bv.y);
            }
        }

        if (ct == 12) {   // keys >= 784 invalid (j groups 2..7 of last chunk)
#pragma unroll
            for (int j = 2; j < 8; j++)
#pragma unroll
                for (int i = 0; i < 4; i++) sacc[j][i] = -1e30f;
        }

        // online softmax — row g uses [0],[1]; row g+8 uses [2],[3]
        float t0m = -1e30f, t1m = -1e30f;
#pragma unroll
        for (int j = 0; j < 8; j++) {
            t0m = fmaxf(t0m, fmaxf(sacc[j][0], sacc[j][1]));
            t1m = fmaxf(t1m, fmaxf(sacc[j][2], sacc[j][3]));
        }
        t0m = fmaxf(t0m, __shfl_xor_sync(0xffffffffu, t0m, 1));
        t0m = fmaxf(t0m, __shfl_xor_sync(0xffffffffu, t0m, 2));
        t1m = fmaxf(t1m, __shfl_xor_sync(0xffffffffu, t1m, 1));
        t1m = fmaxf(t1m, __shfl_xor_sync(0xffffffffu, t1m, 2));
        float mn0 = fmaxf(m0, t0m), mn1 = fmaxf(m1, t1m);
        float sc0 = __expf(m0 - mn0), sc1 = __expf(m1 - mn1);
        m0 = mn0; m1 = mn1;
        l0 *= sc0; l1 *= sc1;
        float ps0 = 0.f, ps1 = 0.f;
#pragma unroll
        for (int j = 0; j < 8; j++) {
            oacc[j][0] *= sc0; oacc[j][1] *= sc0;
            oacc[j][2] *= sc1; oacc[j][3] *= sc1;
            sacc[j][0] = __expf(sacc[j][0] - mn0);   // row g,   key tq
            sacc[j][1] = __expf(sacc[j][1] - mn0);   // row g,   key tq+4
            sacc[j][2] = __expf(sacc[j][2] - mn1);   // row g+8, key tq
            sacc[j][3] = __expf(sacc[j][3] - mn1);   // row g+8, key tq+4
            ps0 += sacc[j][0] + sacc[j][1];
            ps1 += sacc[j][2] + sacc[j][3];
        }
        l0 += ps0; l1 += ps1;

        // O += P V : A frag = (A[g][tq], A[g+8][tq], A[g][tq+4], A[g+8][tq+4])
        //          = (sacc[jj][0], sacc[jj][2], sacc[jj][1], sacc[jj][3])
#pragma unroll
        for (int kk = 0; kk < 64; kk += 8) {
            int jj = kk >> 3;
            uint32_t pa0 = f2tf32(sacc[jj][0]);
            uint32_t pa1 = f2tf32(sacc[jj][2]);
            uint32_t pa2 = f2tf32(sacc[jj][1]);
            uint32_t pa3 = f2tf32(sacc[jj][3]);
#pragma unroll
            for (int j = 0; j < 8; j++) {
                uint2 bv = *(const uint2*)&Vs[(j * 8 + g) * STRF + kk + 2 * tq];
                mma_tf32(oacc[j], pa0, pa1, pa2, pa3, bv.x, bv.y);
            }
        }
    }

    // finalize (row sums live on lanes differing in bits 0-1)
    l0 += __shfl_xor_sync(0xffffffffu, l0, 1);
    l0 += __shfl_xor_sync(0xffffffffu, l0, 2);
    l1 += __shfl_xor_sync(0xffffffffu, l1, 1);
    l1 += __shfl_xor_sync(0xffffffffu, l1, 2);
    float inv0 = 1.f / l0, inv1 = 1.f / l1;

    int b = bh / NHh, h = bh - (bh / NHh) * NHh;
    int r0g = q0 + warp * 16 + g, r1g = r0g + 8;
    if (r0g < Tt) {
        float* dst = g_o + ((size_t)b * Tt + r0g) * Cc + h * HDd;
#pragma unroll
        for (int j = 0; j < 8; j++)
            *(float2*)(dst + j * 8 + 2 * tq) =
                make_float2(oacc[j][0] * inv0, oacc[j][1] * inv0);
    }
    if (r1g < Tt) {
        float* dst = g_o + ((size_t)b * Tt + r1g) * Cc + h * HDd;
#pragma unroll
        for (int j = 0; j < 8; j++)
            *(float2*)(dst + j * 8 + 2 * tq) =
                make_float2(oacc[j][2] * inv1, oacc[j][3] * inv1);
    }
}

// ---------------------------------------------------------------------------
// kernel_launch
// ---------------------------------------------------------------------------
extern "C" void kernel_launch(void* const* d_in, const int* in_sizes, int n_in,
                              void* d_out, int out_size)
{
    int base = 1;
    if (n_in >= 3 && in_sizes[1] == 1 && in_sizes[2] == 1) base = 3;

    const float* x = (const float*)d_in[0];
    const float* cw[3];
    const float* ga[3];
    const float* be[3];
    const float* me[3];
    const float* va[3];
    for (int i = 0; i < 3; i++) {
        cw[i] = (const float*)d_in[base + 5 * i + 0];
        ga[i] = (const float*)d_in[base + 5 * i + 1];
        be[i] = (const float*)d_in[base + 5 * i + 2];
        me[i] = (const float*)d_in[base + 5 * i + 3];
        va[i] = (const float*)d_in[base + 5 * i + 4];
    }
    const float* w_q    = (const float*)d_in[base + 15];
    const float* w_k    = (const float*)d_in[base + 16];
    const float* w_v    = (const float*)d_in[base + 17];
    const float* w_proj = (const float*)d_in[base + 18];
    const float* b_proj = (const float*)d_in[base + 19];
    float* out = (float*)d_out;

    convbn_kernel<<<(Mm * Cc + 255) / 256, 256>>>(
        x,
        cw[0], ga[0], be[0], me[0], va[0],
        cw[1], ga[1], be[1], me[1], va[1],
        cw[2], ga[2], be[2], me[2], va[2]);

    dim3 gg(Mm / 128, Cc / 128);
    qkv_mma_kernel<<<gg, 256>>>(w_q, 0);
    qkv_mma_kernel<<<gg, 256>>>(w_k, 1);
    qkv_mma_kernel<<<gg, 256>>>(w_v, 2);

    flash_kernel<<<dim3(13, BH), 128>>>();

    proj_mma_kernel<<<gg, 256>>>(w_proj, b_proj, out);
}

// round 6
// speedup vs baseline: 3.5788x; 1.1674x over previous
#include <cuda_runtime.h>
#include <cuda_bf16.h>
#include <cstdint>

// Problem constants
#define Bq 32
#define Tt 784
#define Cc 384
#define NHh 6
#define HDd 64
#define Mm (Bq * Tt)          // 25088
#define TP 832                // T padded to 13*64
#define BH (Bq * NHh)         // 192
#define IMG_H 28
#define IMG_W 28
#define SCALE_F 0.05103103630798288f   // 384^-0.5
#define QSCALE (SCALE_F * 1.4426950408889634f)   // fold log2(e) for exp2 softmax

// ---------------------------------------------------------------------------
// Scratch
// ---------------------------------------------------------------------------
__device__ float g_qt[(size_t)Mm * Cc];
__device__ float g_kt[(size_t)Mm * Cc];
__device__ float g_vt[(size_t)Mm * Cc];
__device__ float g_qp[(size_t)BH * TP * HDd];  // [bh][t][d] plain, scaled by QSCALE
__device__ float g_kp[(size_t)BH * TP * HDd];  // [bh][t][d-permuted] tf32 bits
__device__ float g_vT[(size_t)BH * HDd * TP];  // [bh][d][t-permuted] tf32 bits
__device__ float g_o [(size_t)Mm * Cc];        // attention out [b,t,c]

// ---------------------------------------------------------------------------
// conv + BN
// ---------------------------------------------------------------------------
__global__ void __launch_bounds__(256) convbn_kernel(
    const float* __restrict__ x,
    const float* __restrict__ cwq, const float* __restrict__ gq,
    const float* __restrict__ beq, const float* __restrict__ meq,
    const float* __restrict__ vaq,
    const float* __restrict__ cwk, const float* __restrict__ gk,
    const float* __restrict__ bek, const float* __restrict__ mek,
    const float* __restrict__ vak,
    const float* __restrict__ cwv, const float* __restrict__ gv,
    const float* __restrict__ bev, const float* __restrict__ mev,
    const float* __restrict__ vav)
{
    int idx = blockIdx.x * 256 + threadIdx.x;
    if (idx >= Mm * Cc) return;
    int c  = idx % Cc;
    int bt = idx / Cc;
    int t  = bt % Tt;
    int b  = bt / Tt;
    int y  = t / IMG_W;
    int xp = t % IMG_W;

    float vals[9];
#pragma unroll
    for (int dy = 0; dy < 3; dy++) {
#pragma unroll
        for (int dx = 0; dx < 3; dx++) {
            int yy = y + dy - 1, xx = xp + dx - 1;
            bool in = (yy >= 0) && (yy < IMG_H) && (xx >= 0) && (xx < IMG_W);
            vals[dy * 3 + dx] =
                in ? x[((size_t)b * Tt + yy * IMG_W + xx) * Cc + c] : 0.f;
        }
    }
    {
        float acc = 0.f;
#pragma unroll
        for (int i = 0; i < 9; i++) acc += vals[i] * cwq[c * 9 + i];
        float inv = gq[c] * rsqrtf(vaq[c] + 1e-5f);
        g_qt[idx] = acc * inv + (beq[c] - meq[c] * inv);
    }
    {
        float acc = 0.f;
#pragma unroll
        for (int i = 0; i < 9; i++) acc += vals[i] * cwk[c * 9 + i];
        float inv = gk[c] * rsqrtf(vak[c] + 1e-5f);
        g_kt[idx] = acc * inv + (bek[c] - mek[c] * inv);
    }
    {
        float acc = 0.f;
#pragma unroll
        for (int i = 0; i < 9; i++) acc += vals[i] * cwv[c * 9 + i];
        float inv = gv[c] * rsqrtf(vav[c] + 1e-5f);
        g_vt[idx] = acc * inv + (bev[c] - mev[c] * inv);
    }
}

// ---------------------------------------------------------------------------
// tf32 mma helpers
// ---------------------------------------------------------------------------
__device__ __forceinline__ uint32_t f2tf32(float f) {
    uint32_t u;
    asm("cvt.rna.tf32.f32 %0, %1;" : "=r"(u) : "f"(f));
    return u;
}

__device__ __forceinline__ void mma_tf32(float c[4],
    uint32_t a0, uint32_t a1, uint32_t a2, uint32_t a3,
    uint32_t b0, uint32_t b1)
{
    asm volatile(
        "mma.sync.aligned.m16n8k8.row.col.f32.tf32.tf32.f32 "
        "{%0,%1,%2,%3}, {%4,%5,%6,%7}, {%8,%9}, {%0,%1,%2,%3};"
        : "+f"(c[0]), "+f"(c[1]), "+f"(c[2]), "+f"(c[3])
        : "r"(a0), "r"(a1), "r"(a2), "r"(a3), "r"(b0), "r"(b1));
}

__device__ __forceinline__ int pos16(int k) {
    return (k & 8) | ((k & 3) << 1) | ((k & 4) >> 2);
}
__device__ __forceinline__ int perm8(int n) {
    return (n >> 1) + ((n & 1) << 2);
}

__device__ __forceinline__ void store_perm8(uint32_t* dst_row, int kb,
                                            float4 lo, float4 hi) {
    uint2* d = (uint2*)(dst_row + kb);
    d[0] = make_uint2(f2tf32(lo.x), f2tf32(hi.x));
    d[1] = make_uint2(f2tf32(lo.y), f2tf32(hi.y));
    d[2] = make_uint2(f2tf32(lo.z), f2tf32(hi.z));
    d[3] = make_uint2(f2tf32(lo.w), f2tf32(hi.w));
}

__device__ __forceinline__ void cp_async16(uint32_t saddr, const void* gaddr) {
    asm volatile("cp.async.cg.shared.global [%0], [%1], 16;"
                 :: "r"(saddr), "l"(gaddr));
}

// ---------------------------------------------------------------------------
// GEMM core: 128x128 tile, NT, K mult of 16. 256 threads.
// ---------------------------------------------------------------------------
#define STRG 24
#define GEMM_SM (128 * STRG)

__device__ __forceinline__ void gemm128_core(
    const float* __restrict__ A, const float* __restrict__ B,
    int lda, int ldb, int K, int bm, int bn,
    uint32_t* As, uint32_t* Bs, float acc[4][4][4])
{
    const int tid  = threadIdx.x;
    const int lane = tid & 31;
    const int warp = tid >> 5;
    const int g    = lane >> 2;
    const int tq   = lane & 3;
    const int wm   = (warp & 1) * 64;
    const int wn   = (warp >> 1) * 32;
    const int lrow = tid >> 1;
    const int lkb  = (tid & 1) * 8;

    const float* Ag = A + (size_t)(bm + lrow) * lda + lkb;
    const float* Bg = B + (size_t)(bn + lrow) * ldb + lkb;

    float4 pa0 = *(const float4*)Ag;
    float4 pa1 = *(const float4*)(Ag + 4);
    float4 pb0 = *(const float4*)Bg;
    float4 pb1 = *(const float4*)(Bg + 4);

    const int nslab = K >> 4;
    for (int s = 0; s < nslab; s++) {
        uint32_t* Ab = As + (s & 1) * GEMM_SM;
        uint32_t* Bb = Bs + (s & 1) * GEMM_SM;
        store_perm8(Ab + lrow * STRG, lkb, pa0, pa1);
        store_perm8(Bb + lrow * STRG, lkb, pb0, pb1);
        if (s + 1 < nslab) {
            const float* Agn = Ag + (s + 1) * 16;
            const float* Bgn = Bg + (s + 1) * 16;
            pa0 = *(const float4*)Agn;
            pa1 = *(const float4*)(Agn + 4);
            pb0 = *(const float4*)Bgn;
            pb1 = *(const float4*)(Bgn + 4);
        }
        __syncthreads();
#pragma unroll
        for (int kk = 0; kk < 16; kk += 8) {
            uint32_t a[4][4];
#pragma unroll
            for (int ms = 0; ms < 4; ms++) {
                uint2 lo = *(const uint2*)&Ab[(wm + ms * 16 + g) * STRG + kk + 2 * tq];
                uint2 hi = *(const uint2*)&Ab[(wm + ms * 16 + g + 8) * STRG + kk + 2 * tq];
                a[ms][0] = lo.x; a[ms][2] = lo.y;
                a[ms][1] = hi.x; a[ms][3] = hi.y;
            }
#pragma unroll
            for (int j = 0; j < 4; j++) {
                uint2 bv = *(const uint2*)&Bb[(wn + j * 8 + g) * STRG + kk + 2 * tq];
#pragma unroll
                for (int ms = 0; ms < 4; ms++)
                    mma_tf32(acc[ms][j], a[ms][0], a[ms][1], a[ms][2], a[ms][3],
                             bv.x, bv.y);
            }
        }
        __syncthreads();
    }
}

// ---------------------------------------------------------------------------
// Q/K/V projection (single launch, blockIdx.z selects q/k/v);
// K and V written pre-permuted + tf32-rounded; Q scaled by QSCALE
// ---------------------------------------------------------------------------
__global__ void __launch_bounds__(256) qkv_mma_kernel(
    const float* __restrict__ Wq, const float* __restrict__ Wk,
    const float* __restrict__ Wv)
{
    __shared__ uint32_t As[2 * GEMM_SM];
    __shared__ uint32_t Bs[2 * GEMM_SM];
    int which = blockIdx.z;
    const float* A = (which == 0) ? g_qt : (which == 1) ? g_kt : g_vt;
    const float* W = (which == 0) ? Wq   : (which == 1) ? Wk   : Wv;

    int bm = blockIdx.x * 128, bn = blockIdx.y * 128;
    float acc[4][4][4] = {};
    gemm128_core(A, W, Cc, Cc, Cc, bm, bn, As, Bs, acc);

    int lane = threadIdx.x & 31, warp = threadIdx.x >> 5;
    int g = lane >> 2, tq = lane & 3;
    int wm = (warp & 1) * 64, wn = (warp >> 1) * 32;
    int h = (bn + wn) >> 6;

#pragma unroll
    for (int ms = 0; ms < 4; ms++) {
#pragma unroll
        for (int rr = 0; rr < 2; rr++) {
            int m = bm + wm + ms * 16 + g + rr * 8;
            int b = m / Tt, t = m - b * Tt;
            int bh = b * NHh + h;
            if (which == 0) {
                float* dst = g_qp + ((size_t)bh * TP + t) * HDd;
#pragma unroll
                for (int j = 0; j < 4; j++) {
                    int d = (bn + wn + j * 8 + 2 * tq) & 63;
                    *(float2*)(dst + d) = make_float2(
                        acc[ms][j][rr * 2 + 0] * QSCALE,
                        acc[ms][j][rr * 2 + 1] * QSCALE);
                }
            } else if (which == 1) {
                float* dst = g_kp + ((size_t)bh * TP + t) * HDd;
#pragma unroll
                for (int j = 0; j < 4; j++) {
                    int c0 = (bn + wn + j * 8 + 2 * tq) & 63;
                    int p0 = (c0 & 48) | pos16(c0 & 15);
                    int p1 = (c0 & 48) | pos16((c0 + 1) & 15);
                    dst[p0] = __uint_as_float(f2tf32(acc[ms][j][rr * 2 + 0]));
                    dst[p1] = __uint_as_float(f2tf32(acc[ms][j][rr * 2 + 1]));
                }
            } else {
                int tp = (t & ~15) | pos16(t & 15);
                float* dst = g_vT + (size_t)bh * HDd * TP + tp;
#pragma unroll
                for (int j = 0; j < 4; j++) {
                    int d = (bn + wn + j * 8 + 2 * tq) & 63;
                    dst[(size_t)d * TP] =
                        __uint_as_float(f2tf32(acc[ms][j][rr * 2 + 0]));
                    dst[(size_t)(d + 1) * TP] =
                        __uint_as_float(f2tf32(acc[ms][j][rr * 2 + 1]));
                }
            }
        }
    }
}

// ---------------------------------------------------------------------------
// Output projection
// ---------------------------------------------------------------------------
__global__ void __launch_bounds__(256) proj_mma_kernel(
    const float* __restrict__ W, const float* __restrict__ bias,
    float* __restrict__ out)
{
    __shared__ uint32_t As[2 * GEMM_SM];
    __shared__ uint32_t Bs[2 * GEMM_SM];
    int bm = blockIdx.x * 128, bn = blockIdx.y * 128;
    float acc[4][4][4] = {};
    gemm128_core(g_o, W, Cc, Cc, Cc, bm, bn, As, Bs, acc);

    int lane = threadIdx.x & 31, warp = threadIdx.x >> 5;
    int g = lane >> 2, tq = lane & 3;
    int wm = (warp & 1) * 64, wn = (warp >> 1) * 32;
#pragma unroll
    for (int ms = 0; ms < 4; ms++) {
#pragma unroll
        for (int rr = 0; rr < 2; rr++) {
            int m = bm + wm + ms * 16 + g + rr * 8;
#pragma unroll
            for (int j = 0; j < 4; j++) {
                int n = bn + wn + j * 8 + 2 * tq;
                float2 bb = *(const float2*)(bias + n);
                *(float2*)(out + (size_t)m * Cc + n) = make_float2(
                    acc[ms][j][rr * 2 + 0] + bb.x,
                    acc[ms][j][rr * 2 + 1] + bb.y);
            }
        }
    }
}

// ---------------------------------------------------------------------------
// Flash attention. Block = (bh, 64 q rows), 128 threads.
// cp.async double-buffered K/V staging; softmax in exp2 domain;
// P stays in registers (S accumulator fragment == PV A fragment).
// ---------------------------------------------------------------------------
#define STRF 72
#define FBUF (64 * STRF)

__global__ void __launch_bounds__(128) flash_kernel()
{
    __shared__ uint32_t Ks[2 * FBUF];
    __shared__ uint32_t Vs[2 * FBUF];

    int bh = blockIdx.y;
    int q0 = blockIdx.x * 64;
    int tid = threadIdx.x, lane = tid & 31, warp = tid >> 5;
    int g = lane >> 2, tq = lane & 3;

    const float* Qb = g_qp + (size_t)bh * TP * HDd;
    const float* Kb = g_kp + (size_t)bh * TP * HDd;
    const float* Vb = g_vT + (size_t)bh * HDd * TP;

    const int lrow = tid >> 1;
    const int lh   = (tid & 1) * 32;
    const int krow = (lrow & ~7) | perm8(lrow & 7);

    const float* ksrc = Kb + (size_t)krow * HDd + lh;
    const float* vsrc = Vb + (size_t)lrow * TP + lh;
    uint32_t kbase, vbase;
    {
        uint64_t ka = __cvta_generic_to_shared(Ks + lrow * STRF + lh);
        uint64_t va = __cvta_generic_to_shared(Vs + lrow * STRF + lh);
        kbase = (uint32_t)ka;
        vbase = (uint32_t)va;
    }

    // issue one chunk's K+V copies into buffer (ct&1)
    auto issue_chunk = [&](int ct) {
        uint32_t off = (ct & 1) * (FBUF * 4);
        const float* kp = ksrc + (size_t)ct * 64 * HDd;
        const float* vp = vsrc + ct * 64;
#pragma unroll
        for (int i = 0; i < 8; i++) {
            cp_async16(kbase + off + i * 16, kp + i * 4);
            cp_async16(vbase + off + i * 16, vp + i * 4);
        }
        asm volatile("cp.async.commit_group;");
    };

    // Q fragments in registers (plain layout)
    uint32_t qf[8][4];
    {
        const float* r0 = Qb + (size_t)(q0 + warp * 16 + g) * HDd;
        const float* r1 = r0 + 8 * HDd;
#pragma unroll
        for (int k8 = 0; k8 < 8; k8++) {
            qf[k8][0] = f2tf32(r0[k8 * 8 + tq]);
            qf[k8][2] = f2tf32(r0[k8 * 8 + tq + 4]);
            qf[k8][1] = f2tf32(r1[k8 * 8 + tq]);
            qf[k8][3] = f2tf32(r1[k8 * 8 + tq + 4]);
        }
    }

    issue_chunk(0);
    issue_chunk(1);

    float oacc[8][4];
#pragma unroll
    for (int j = 0; j < 8; j++)
#pragma unroll
        for (int i = 0; i < 4; i++) oacc[j][i] = 0.f;
    float m0 = -1e30f, m1 = -1e30f, l0 = 0.f, l1 = 0.f;

    for (int ct = 0; ct < 13; ct++) {
        if (ct < 12) asm volatile("cp.async.wait_group 1;");
        else         asm volatile("cp.async.wait_group 0;");
        __syncthreads();

        const uint32_t* Kbuf = Ks + (ct & 1) * FBUF;
        const uint32_t* Vbuf = Vs + (ct & 1) * FBUF;

        // S = Q K^T (exp2 domain: q pre-scaled by SCALE*log2e)
        float sacc[8][4];
#pragma unroll
        for (int j = 0; j < 8; j++)
#pragma unroll
            for (int i = 0; i < 4; i++) sacc[j][i] = 0.f;
#pragma unroll
        for (int kk = 0; kk < 64; kk += 8) {
#pragma unroll
            for (int j = 0; j < 8; j++) {
                uint2 bv = *(const uint2*)&Kbuf[(j * 8 + g) * STRF + kk + 2 * tq];
                mma_tf32(sacc[j], qf[kk >> 3][0], qf[kk >> 3][1],
                         qf[kk >> 3][2], qf[kk >> 3][3], bv.x, bv.y);
            }
        }

        if (ct == 12) {   // keys >= 784 invalid
#pragma unroll
            for (int j = 2; j < 8; j++)
#pragma unroll
                for (int i = 0; i < 4; i++) sacc[j][i] = -1e30f;
        }

        // online softmax — row g: [0],[1]; row g+8: [2],[3]
        float t0m = -1e30f, t1m = -1e30f;
#pragma unroll
        for (int j = 0; j < 8; j++) {
            t0m = fmaxf(t0m, fmaxf(sacc[j][0], sacc[j][1]));
            t1m = fmaxf(t1m, fmaxf(sacc[j][2], sacc[j][3]));
        }
        t0m = fmaxf(t0m, __shfl_xor_sync(0xffffffffu, t0m, 1));
        t0m = fmaxf(t0m, __shfl_xor_sync(0xffffffffu, t0m, 2));
        t1m = fmaxf(t1m, __shfl_xor_sync(0xffffffffu, t1m, 1));
        t1m = fmaxf(t1m, __shfl_xor_sync(0xffffffffu, t1m, 2));
        float mn0 = fmaxf(m0, t0m), mn1 = fmaxf(m1, t1m);
        float sc0 = exp2f(m0 - mn0), sc1 = exp2f(m1 - mn1);
        m0 = mn0; m1 = mn1;
        l0 *= sc0; l1 *= sc1;
        float ps0 = 0.f, ps1 = 0.f;
#pragma unroll
        for (int j = 0; j < 8; j++) {
            oacc[j][0] *= sc0; oacc[j][1] *= sc0;
            oacc[j][2] *= sc1; oacc[j][3] *= sc1;
            sacc[j][0] = exp2f(sacc[j][0] - mn0);
            sacc[j][1] = exp2f(sacc[j][1] - mn0);
            sacc[j][2] = exp2f(sacc[j][2] - mn1);
            sacc[j][3] = exp2f(sacc[j][3] - mn1);
            ps0 += sacc[j][0] + sacc[j][1];
            ps1 += sacc[j][2] + sacc[j][3];
        }
        l0 += ps0; l1 += ps1;

        // O += P V
#pragma unroll
        for (int kk = 0; kk < 64; kk += 8) {
            int jj = kk >> 3;
            uint32_t pa0 = f2tf32(sacc[jj][0]);
            uint32_t pa1 = f2tf32(sacc[jj][2]);
            uint32_t pa2 = f2tf32(sacc[jj][1]);
            uint32_t pa3 = f2tf32(sacc[jj][3]);
#pragma unroll
            for (int j = 0; j < 8; j++) {
                uint2 bv = *(const uint2*)&Vbuf[(j * 8 + g) * STRF + kk + 2 * tq];
                mma_tf32(oacc[j], pa0, pa1, pa2, pa3, bv.x, bv.y);
            }
        }

        __syncthreads();   // buffer (ct&1) fully consumed by all warps
        if (ct + 2 < 13) issue_chunk(ct + 2);
    }

    // finalize
    l0 += __shfl_xor_sync(0xffffffffu, l0, 1);
    l0 += __shfl_xor_sync(0xffffffffu, l0, 2);
    l1 += __shfl_xor_sync(0xffffffffu, l1, 1);
    l1 += __shfl_xor_sync(0xffffffffu, l1, 2);
    float inv0 = 1.f / l0, inv1 = 1.f / l1;

    int b = bh / NHh, h = bh - (bh / NHh) * NHh;
    int r0g = q0 + warp * 16 + g, r1g = r0g + 8;
    if (r0g < Tt) {
        float* dst = g_o + ((size_t)b * Tt + r0g) * Cc + h * HDd;
#pragma unroll
        for (int j = 0; j < 8; j++)
            *(float2*)(dst + j * 8 + 2 * tq) =
                make_float2(oacc[j][0] * inv0, oacc[j][1] * inv0);
    }
    if (r1g < Tt) {
        float* dst = g_o + ((size_t)b * Tt + r1g) * Cc + h * HDd;
#pragma unroll
        for (int j = 0; j < 8; j++)
            *(float2*)(dst + j * 8 + 2 * tq) =
                make_float2(oacc[j][2] * inv1, oacc[j][3] * inv1);
    }
}

// ---------------------------------------------------------------------------
// kernel_launch
// ---------------------------------------------------------------------------
extern "C" void kernel_launch(void* const* d_in, const int* in_sizes, int n_in,
                              void* d_out, int out_size)
{
    int base = 1;
    if (n_in >= 3 && in_sizes[1] == 1 && in_sizes[2] == 1) base = 3;

    const float* x = (const float*)d_in[0];
    const float* cw[3];
    const float* ga[3];
    const float* be[3];
    const float* me[3];
    const float* va[3];
    for (int i = 0; i < 3; i++) {
        cw[i] = (const float*)d_in[base + 5 * i + 0];
        ga[i] = (const float*)d_in[base + 5 * i + 1];
        be[i] = (const float*)d_in[base + 5 * i + 2];
        me[i] = (const float*)d_in[base + 5 * i + 3];
        va[i] = (const float*)d_in[base + 5 * i + 4];
    }
    const float* w_q    = (const float*)d_in[base + 15];
    const float* w_k    = (const float*)d_in[base + 16];
    const float* w_v    = (const float*)d_in[base + 17];
    const float* w_proj = (const float*)d_in[base + 18];
    const float* b_proj = (const float*)d_in[base + 19];
    float* out = (float*)d_out;

    convbn_kernel<<<(Mm * Cc + 255) / 256, 256>>>(
        x,
        cw[0], ga[0], be[0], me[0], va[0],
        cw[1], ga[1], be[1], me[1], va[1],
        cw[2], ga[2], be[2], me[2], va[2]);

    qkv_mma_kernel<<<dim3(Mm / 128, Cc / 128, 3), 256>>>(w_q, w_k, w_v);

    flash_kernel<<<dim3(13, BH), 128>>>();

    proj_mma_kernel<<<dim3(Mm / 128, Cc / 128), 256>>>(w_proj, b_proj, out);
}

// round 8
// speedup vs baseline: 4.1742x; 1.1664x over previous
#include <cuda_runtime.h>
#include <cuda_bf16.h>
#include <cstdint>

// Problem constants
#define Bq 32
#define Tt 784
#define Cc 384
#define NHh 6
#define HDd 64
#define Mm (Bq * Tt)          // 25088
#define TP 832                // T padded to 13*64
#define BH (Bq * NHh)         // 192
#define IMG_H 28
#define IMG_W 28
#define SCALE_F 0.05103103630798288f   // 384^-0.5
#define QSCALE (SCALE_F * 1.4426950408889634f)   // fold log2(e) for exp2 softmax

// ---------------------------------------------------------------------------
// Scratch
// ---------------------------------------------------------------------------
__device__ float g_qt[(size_t)Mm * Cc];
__device__ float g_kt[(size_t)Mm * Cc];
__device__ float g_vt[(size_t)Mm * Cc];
__device__ float g_qp[(size_t)BH * TP * HDd];  // [bh][t][d] plain, scaled by QSCALE
__device__ float g_kp[(size_t)BH * TP * HDd];  // [bh][t][d-permuted] tf32 bits
__device__ float g_vT[(size_t)BH * HDd * TP];  // [bh][d][t-permuted] tf32 bits
__device__ float g_o [(size_t)Mm * Cc];        // attention out [b,t,c]

// ---------------------------------------------------------------------------
// conv + BN
// ---------------------------------------------------------------------------
__global__ void __launch_bounds__(256) convbn_kernel(
    const float* __restrict__ x,
    const float* __restrict__ cwq, const float* __restrict__ gq,
    const float* __restrict__ beq, const float* __restrict__ meq,
    const float* __restrict__ vaq,
    const float* __restrict__ cwk, const float* __restrict__ gk,
    const float* __restrict__ bek, const float* __restrict__ mek,
    const float* __restrict__ vak,
    const float* __restrict__ cwv, const float* __restrict__ gv,
    const float* __restrict__ bev, const float* __restrict__ mev,
    const float* __restrict__ vav)
{
    int idx = blockIdx.x * 256 + threadIdx.x;
    if (idx >= Mm * Cc) return;
    int c  = idx % Cc;
    int bt = idx / Cc;
    int t  = bt % Tt;
    int b  = bt / Tt;
    int y  = t / IMG_W;
    int xp = t % IMG_W;

    float vals[9];
#pragma unroll
    for (int dy = 0; dy < 3; dy++) {
#pragma unroll
        for (int dx = 0; dx < 3; dx++) {
            int yy = y + dy - 1, xx = xp + dx - 1;
            bool in = (yy >= 0) && (yy < IMG_H) && (xx >= 0) && (xx < IMG_W);
            vals[dy * 3 + dx] =
                in ? x[((size_t)b * Tt + yy * IMG_W + xx) * Cc + c] : 0.f;
        }
    }
    {
        float acc = 0.f;
#pragma unroll
        for (int i = 0; i < 9; i++) acc += vals[i] * cwq[c * 9 + i];
        float inv = gq[c] * rsqrtf(vaq[c] + 1e-5f);
        g_qt[idx] = acc * inv + (beq[c] - meq[c] * inv);
    }
    {
        float acc = 0.f;
#pragma unroll
        for (int i = 0; i < 9; i++) acc += vals[i] * cwk[c * 9 + i];
        float inv = gk[c] * rsqrtf(vak[c] + 1e-5f);
        g_kt[idx] = acc * inv + (bek[c] - mek[c] * inv);
    }
    {
        float acc = 0.f;
#pragma unroll
        for (int i = 0; i < 9; i++) acc += vals[i] * cwv[c * 9 + i];
        float inv = gv[c] * rsqrtf(vav[c] + 1e-5f);
        g_vt[idx] = acc * inv + (bev[c] - mev[c] * inv);
    }
}

// ---------------------------------------------------------------------------
// tf32 mma helpers
// ---------------------------------------------------------------------------
__device__ __forceinline__ uint32_t f2tf32(float f) {
    uint32_t u;
    asm("cvt.rna.tf32.f32 %0, %1;" : "=r"(u) : "f"(f));
    return u;
}

__device__ __forceinline__ void mma_tf32(float c[4],
    uint32_t a0, uint32_t a1, uint32_t a2, uint32_t a3,
    uint32_t b0, uint32_t b1)
{
    asm volatile(
        "mma.sync.aligned.m16n8k8.row.col.f32.tf32.tf32.f32 "
        "{%0,%1,%2,%3}, {%4,%5,%6,%7}, {%8,%9}, {%0,%1,%2,%3};"
        : "+f"(c[0]), "+f"(c[1]), "+f"(c[2]), "+f"(c[3])
        : "r"(a0), "r"(a1), "r"(a2), "r"(a3), "r"(b0), "r"(b1));
}

__device__ __forceinline__ int pos16(int k) {
    return (k & 8) | ((k & 3) << 1) | ((k & 4) >> 2);
}
__device__ __forceinline__ int perm8(int n) {
    return (n >> 1) + ((n & 1) << 2);
}

__device__ __forceinline__ void store_perm8(uint32_t* dst_row, int kb,
                                            float4 lo, float4 hi) {
    uint2* d = (uint2*)(dst_row + kb);
    d[0] = make_uint2(f2tf32(lo.x), f2tf32(hi.x));
    d[1] = make_uint2(f2tf32(lo.y), f2tf32(hi.y));
    d[2] = make_uint2(f2tf32(lo.z), f2tf32(hi.z));
    d[3] = make_uint2(f2tf32(lo.w), f2tf32(hi.w));
}

__device__ __forceinline__ void cp_async16(uint32_t saddr, const void* gaddr) {
    asm volatile("cp.async.cg.shared.global [%0], [%1], 16;"
                 :: "r"(saddr), "l"(gaddr));
}

__device__ __forceinline__ uint32_t smem_u32(const void* p) {
    return (uint32_t)__cvta_generic_to_shared(p);
}

// ---------------------------------------------------------------------------
// GEMM core: 128x128 tile, NT, K mult of 16. 256 threads. (unchanged, passing)
// ---------------------------------------------------------------------------
#define STRG 24
#define GEMM_SM (128 * STRG)

__device__ __forceinline__ void gemm128_core(
    const float* __restrict__ A, const float* __restrict__ B,
    int lda, int ldb, int K, int bm, int bn,
    uint32_t* As, uint32_t* Bs, float acc[4][4][4])
{
    const int tid  = threadIdx.x;
    const int lane = tid & 31;
    const int warp = tid >> 5;
    const int g    = lane >> 2;
    const int tq   = lane & 3;
    const int wm   = (warp & 1) * 64;
    const int wn   = (warp >> 1) * 32;
    const int lrow = tid >> 1;
    const int lkb  = (tid & 1) * 8;

    const float* Ag = A + (size_t)(bm + lrow) * lda + lkb;
    const float* Bg = B + (size_t)(bn + lrow) * ldb + lkb;

    float4 pa0 = *(const float4*)Ag;
    float4 pa1 = *(const float4*)(Ag + 4);
    float4 pb0 = *(const float4*)Bg;
    float4 pb1 = *(const float4*)(Bg + 4);

    const int nslab = K >> 4;
    for (int s = 0; s < nslab; s++) {
        uint32_t* Ab = As + (s & 1) * GEMM_SM;
        uint32_t* Bb = Bs + (s & 1) * GEMM_SM;
        store_perm8(Ab + lrow * STRG, lkb, pa0, pa1);
        store_perm8(Bb + lrow * STRG, lkb, pb0, pb1);
        if (s + 1 < nslab) {
            const float* Agn = Ag + (s + 1) * 16;
            const float* Bgn = Bg + (s + 1) * 16;
            pa0 = *(const float4*)Agn;
            pa1 = *(const float4*)(Agn + 4);
            pb0 = *(const float4*)Bgn;
            pb1 = *(const float4*)(Bgn + 4);
        }
        __syncthreads();
#pragma unroll
        for (int kk = 0; kk < 16; kk += 8) {
            uint32_t a[4][4];
#pragma unroll
            for (int ms = 0; ms < 4; ms++) {
                uint2 lo = *(const uint2*)&Ab[(wm + ms * 16 + g) * STRG + kk + 2 * tq];
                uint2 hi = *(const uint2*)&Ab[(wm + ms * 16 + g + 8) * STRG + kk + 2 * tq];
                a[ms][0] = lo.x; a[ms][2] = lo.y;
                a[ms][1] = hi.x; a[ms][3] = hi.y;
            }
#pragma unroll
            for (int j = 0; j < 4; j++) {
                uint2 bv = *(const uint2*)&Bb[(wn + j * 8 + g) * STRG + kk + 2 * tq];
#pragma unroll
                for (int ms = 0; ms < 4; ms++)
                    mma_tf32(acc[ms][j], a[ms][0], a[ms][1], a[ms][2], a[ms][3],
                             bv.x, bv.y);
            }
        }
        __syncthreads();
    }
}

// ---------------------------------------------------------------------------
// Q/K/V projection (blockIdx.z selects q/k/v); K/V pre-permuted + tf32
// ---------------------------------------------------------------------------
__global__ void __launch_bounds__(256) qkv_mma_kernel(
    const float* __restrict__ Wq, const float* __restrict__ Wk,
    const float* __restrict__ Wv)
{
    __shared__ uint32_t As[2 * GEMM_SM];
    __shared__ uint32_t Bs[2 * GEMM_SM];
    int which = blockIdx.z;
    const float* A = (which == 0) ? g_qt : (which == 1) ? g_kt : g_vt;
    const float* W = (which == 0) ? Wq   : (which == 1) ? Wk   : Wv;

    int bm = blockIdx.x * 128, bn = blockIdx.y * 128;
    float acc[4][4][4] = {};
    gemm128_core(A, W, Cc, Cc, Cc, bm, bn, As, Bs, acc);

    int lane = threadIdx.x & 31, warp = threadIdx.x >> 5;
    int g = lane >> 2, tq = lane & 3;
    int wm = (warp & 1) * 64, wn = (warp >> 1) * 32;
    int h = (bn + wn) >> 6;

#pragma unroll
    for (int ms = 0; ms < 4; ms++) {
#pragma unroll
        for (int rr = 0; rr < 2; rr++) {
            int m = bm + wm + ms * 16 + g + rr * 8;
            int b = m / Tt, t = m - b * Tt;
            int bh = b * NHh + h;
            if (which == 0) {
                float* dst = g_qp + ((size_t)bh * TP + t) * HDd;
#pragma unroll
                for (int j = 0; j < 4; j++) {
                    int d = (bn + wn + j * 8 + 2 * tq) & 63;
                    *(float2*)(dst + d) = make_float2(
                        acc[ms][j][rr * 2 + 0] * QSCALE,
                        acc[ms][j][rr * 2 + 1] * QSCALE);
                }
            } else if (which == 1) {
                float* dst = g_kp + ((size_t)bh * TP + t) * HDd;
#pragma unroll
                for (int j = 0; j < 4; j++) {
                    int c0 = (bn + wn + j * 8 + 2 * tq) & 63;
                    int p0 = (c0 & 48) | pos16(c0 & 15);
                    int p1 = (c0 & 48) | pos16((c0 + 1) & 15);
                    dst[p0] = __uint_as_float(f2tf32(acc[ms][j][rr * 2 + 0]));
                    dst[p1] = __uint_as_float(f2tf32(acc[ms][j][rr * 2 + 1]));
                }
            } else {
                int tp = (t & ~15) | pos16(t & 15);
                float* dst = g_vT + (size_t)bh * HDd * TP + tp;
#pragma unroll
                for (int j = 0; j < 4; j++) {
                    int d = (bn + wn + j * 8 + 2 * tq) & 63;
                    dst[(size_t)d * TP] =
                        __uint_as_float(f2tf32(acc[ms][j][rr * 2 + 0]));
                    dst[(size_t)(d + 1) * TP] =
                        __uint_as_float(f2tf32(acc[ms][j][rr * 2 + 1]));
                }
            }
        }
    }
}

// ---------------------------------------------------------------------------
// Output projection
// ---------------------------------------------------------------------------
__global__ void __launch_bounds__(256) proj_mma_kernel(
    const float* __restrict__ W, const float* __restrict__ bias,
    float* __restrict__ out)
{
    __shared__ uint32_t As[2 * GEMM_SM];
    __shared__ uint32_t Bs[2 * GEMM_SM];
    int bm = blockIdx.x * 128, bn = blockIdx.y * 128;
    float acc[4][4][4] = {};
    gemm128_core(g_o, W, Cc, Cc, Cc, bm, bn, As, Bs, acc);

    int lane = threadIdx.x & 31, warp = threadIdx.x >> 5;
    int g = lane >> 2, tq = lane & 3;
    int wm = (warp & 1) * 64, wn = (warp >> 1) * 32;
#pragma unroll
    for (int ms = 0; ms < 4; ms++) {
#pragma unroll
        for (int rr = 0; rr < 2; rr++) {
            int m = bm + wm + ms * 16 + g + rr * 8;
#pragma unroll
            for (int j = 0; j < 4; j++) {
                int n = bn + wn + j * 8 + 2 * tq;
                float2 bb = *(const float2*)(bias + n);
                *(float2*)(out + (size_t)m * Cc + n) = make_float2(
                    acc[ms][j][rr * 2 + 0] + bb.x,
                    acc[ms][j][rr * 2 + 1] + bb.y);
            }
        }
    }
}

// ---------------------------------------------------------------------------
// Flash attention. Block = (bh, 128 q rows), 256 threads (8 warps x 16 rows).
// cp.async double-buffered K/V (shared by all 8 warps); exp2 softmax;
// P stays in registers.
// ---------------------------------------------------------------------------
#define STRF 72
#define FBUF (64 * STRF)

__global__ void __launch_bounds__(256) flash_kernel()
{
    __shared__ uint32_t Ks[2 * FBUF];
    __shared__ uint32_t Vs[2 * FBUF];

    int bh = blockIdx.y;
    int q0 = blockIdx.x * 128;
    int tid = threadIdx.x, lane = tid & 31, warp = tid >> 5;
    int g = lane >> 2, tq = lane & 3;

    const float* Qb = g_qp + (size_t)bh * TP * HDd;
    const float* Kb = g_kp + (size_t)bh * TP * HDd;
    const float* Vb = g_vT + (size_t)bh * HDd * TP;

    // staging: 256 threads, each covers a 16-word (64B) segment of one row
    const int lrow = tid >> 2;            // 0..63
    const int lq   = (tid & 3) * 16;      // segment start (words)
    const int krow = (lrow & ~7) | perm8(lrow & 7);

    const float* ksrc = Kb + (size_t)krow * HDd + lq;
    const float* vsrc = Vb + (size_t)lrow * TP + lq;
    uint32_t kbase = smem_u32(Ks + lrow * STRF + lq);
    uint32_t vbase = smem_u32(Vs + lrow * STRF + lq);

    auto issue_chunk = [&](int ct) {
        uint32_t off = (ct & 1) * (FBUF * 4);
        const float* kp = ksrc + (size_t)ct * 64 * HDd;
        const float* vp = vsrc + ct * 64;
#pragma unroll
        for (int i = 0; i < 4; i++) {
            cp_async16(kbase + off + i * 16, kp + i * 4);
            cp_async16(vbase + off + i * 16, vp + i * 4);
        }
        asm volatile("cp.async.commit_group;");
    };

    // Q fragments (rows clamped to 783 to stay in-bounds; outputs guarded)
    uint32_t qf[8][4];
    {
        int r0i = min(q0 + warp * 16 + g, Tt - 1);
        int r1i = min(q0 + warp * 16 + g + 8, Tt - 1);
        const float* r0 = Qb + (size_t)r0i * HDd;
        const float* r1 = Qb + (size_t)r1i * HDd;
#pragma unroll
        for (int k8 = 0; k8 < 8; k8++) {
            qf[k8][0] = f2tf32(r0[k8 * 8 + tq]);
            qf[k8][2] = f2tf32(r0[k8 * 8 + tq + 4]);
            qf[k8][1] = f2tf32(r1[k8 * 8 + tq]);
            qf[k8][3] = f2tf32(r1[k8 * 8 + tq + 4]);
        }
    }

    issue_chunk(0);
    issue_chunk(1);

    float oacc[8][4];
#pragma unroll
    for (int j = 0; j < 8; j++)
#pragma unroll
        for (int i = 0; i < 4; i++) oacc[j][i] = 0.f;
    float m0 = -1e30f, m1 = -1e30f, l0 = 0.f, l1 = 0.f;

    for (int ct = 0; ct < 13; ct++) {
        if (ct < 12) asm volatile("cp.async.wait_group 1;");
        else         asm volatile("cp.async.wait_group 0;");
        __syncthreads();

        const uint32_t* Kbuf = Ks + (ct & 1) * FBUF;
        const uint32_t* Vbuf = Vs + (ct & 1) * FBUF;

        // S = Q K^T
        float sacc[8][4];
#pragma unroll
        for (int j = 0; j < 8; j++)
#pragma unroll
            for (int i = 0; i < 4; i++) sacc[j][i] = 0.f;
#pragma unroll
        for (int kk = 0; kk < 64; kk += 8) {
#pragma unroll
            for (int j = 0; j < 8; j++) {
                uint2 bv = *(const uint2*)&Kbuf[(j * 8 + g) * STRF + kk + 2 * tq];
                mma_tf32(sacc[j], qf[kk >> 3][0], qf[kk >> 3][1],
                         qf[kk >> 3][2], qf[kk >> 3][3], bv.x, bv.y);
            }
        }

        if (ct == 12) {   // keys >= 784 invalid
#pragma unroll
            for (int j = 2; j < 8; j++)
#pragma unroll
                for (int i = 0; i < 4; i++) sacc[j][i] = -1e30f;
        }

        // online softmax — row g: [0],[1]; row g+8: [2],[3]
        float t0m = -1e30f, t1m = -1e30f;
#pragma unroll
        for (int j = 0; j < 8; j++) {
            t0m = fmaxf(t0m, fmaxf(sacc[j][0], sacc[j][1]));
            t1m = fmaxf(t1m, fmaxf(sacc[j][2], sacc[j][3]));
        }
        t0m = fmaxf(t0m, __shfl_xor_sync(0xffffffffu, t0m, 1));
        t0m = fmaxf(t0m, __shfl_xor_sync(0xffffffffu, t0m, 2));
        t1m = fmaxf(t1m, __shfl_xor_sync(0xffffffffu, t1m, 1));
        t1m = fmaxf(t1m, __shfl_xor_sync(0xffffffffu, t1m, 2));
        float mn0 = fmaxf(m0, t0m), mn1 = fmaxf(m1, t1m);
        float sc0 = exp2f(m0 - mn0), sc1 = exp2f(m1 - mn1);
        m0 = mn0; m1 = mn1;
        l0 *= sc0; l1 *= sc1;
        float ps0 = 0.f, ps1 = 0.f;
#pragma unroll
        for (int j = 0; j < 8; j++) {
            oacc[j][0] *= sc0; oacc[j][1] *= sc0;
            oacc[j][2] *= sc1; oacc[j][3] *= sc1;
            sacc[j][0] = exp2f(sacc[j][0] - mn0);
            sacc[j][1] = exp2f(sacc[j][1] - mn0);
            sacc[j][2] = exp2f(sacc[j][2] - mn1);
            sacc[j][3] = exp2f(sacc[j][3] - mn1);
            ps0 += sacc[j][0] + sacc[j][1];
            ps1 += sacc[j][2] + sacc[j][3];
        }
        l0 += ps0; l1 += ps1;

        // O += P V
#pragma unroll
        for (int kk = 0; kk < 64; kk += 8) {
            int jj = kk >> 3;
            uint32_t pa0 = f2tf32(sacc[jj][0]);
            uint32_t pa1 = f2tf32(sacc[jj][2]);
            uint32_t pa2 = f2tf32(sacc[jj][1]);
            uint32_t pa3 = f2tf32(sacc[jj][3]);
#pragma unroll
            for (int j = 0; j < 8; j++) {
                uint2 bv = *(const uint2*)&Vbuf[(j * 8 + g) * STRF + kk + 2 * tq];
                mma_tf32(oacc[j], pa0, pa1, pa2, pa3, bv.x, bv.y);
            }
        }

        __syncthreads();
        if (ct + 2 < 13) issue_chunk(ct + 2);
    }

    // finalize
    l0 += __shfl_xor_sync(0xffffffffu, l0, 1);
    l0 += __shfl_xor_sync(0xffffffffu, l0, 2);
    l1 += __shfl_xor_sync(0xffffffffu, l1, 1);
    l1 += __shfl_xor_sync(0xffffffffu, l1, 2);
    float inv0 = 1.f / l0, inv1 = 1.f / l1;

    int b = bh / NHh, h = bh - (bh / NHh) * NHh;
    int r0g = q0 + warp * 16 + g, r1g = r0g + 8;
    if (r0g < Tt) {
        float* dst = g_o + ((size_t)b * Tt + r0g) * Cc + h * HDd;
#pragma unroll
        for (int j = 0; j < 8; j++)
            *(float2*)(dst + j * 8 + 2 * tq) =
                make_float2(oacc[j][0] * inv0, oacc[j][1] * inv0);
    }
    if (r1g < Tt) {
        float* dst = g_o + ((size_t)b * Tt + r1g) * Cc + h * HDd;
#pragma unroll
        for (int j = 0; j < 8; j++)
            *(float2*)(dst + j * 8 + 2 * tq) =
                make_float2(oacc[j][2] * inv1, oacc[j][3] * inv1);
    }
}

// ---------------------------------------------------------------------------
// kernel_launch
// ---------------------------------------------------------------------------
extern "C" void kernel_launch(void* const* d_in, const int* in_sizes, int n_in,
                              void* d_out, int out_size)
{
    int base = 1;
    if (n_in >= 3 && in_sizes[1] == 1 && in_sizes[2] == 1) base = 3;

    const float* x = (const float*)d_in[0];
    const float* cw[3];
    const float* ga[3];
    const float* be[3];
    const float* me[3];
    const float* va[3];
    for (int i = 0; i < 3; i++) {
        cw[i] = (const float*)d_in[base + 5 * i + 0];
        ga[i] = (const float*)d_in[base + 5 * i + 1];
        be[i] = (const float*)d_in[base + 5 * i + 2];
        me[i] = (const float*)d_in[base + 5 * i + 3];
        va[i] = (const float*)d_in[base + 5 * i + 4];
    }
    const float* w_q    = (const float*)d_in[base + 15];
    const float* w_k    = (const float*)d_in[base + 16];
    const float* w_v    = (const float*)d_in[base + 17];
    const float* w_proj = (const float*)d_in[base + 18];
    const float* b_proj = (const float*)d_in[base + 19];
    float* out = (float*)d_out;

    convbn_kernel<<<(Mm * Cc + 255) / 256, 256>>>(
        x,
        cw[0], ga[0], be[0], me[0], va[0],
        cw[1], ga[1], be[1], me[1], va[1],
        cw[2], ga[2], be[2], me[2], va[2]);

    qkv_mma_kernel<<<dim3(Mm / 128, Cc / 128, 3), 256>>>(w_q, w_k, w_v);

    flash_kernel<<<dim3(7, BH), 256>>>();

    proj_mma_kernel<<<dim3(Mm / 128, Cc / 128), 256>>>(w_proj, b_proj, out);
}

// round 9
// speedup vs baseline: 4.2824x; 1.0259x over previous
#include <cuda_runtime.h>
#include <cuda_bf16.h>
#include <cstdint>

// Problem constants
#define Bq 32
#define Tt 784
#define Cc 384
#define NHh 6
#define HDd 64
#define Mm (Bq * Tt)          // 25088
#define TP 832                // T padded to 13*64
#define BH (Bq * NHh)         // 192
#define IMG_H 28
#define IMG_W 28
#define SCALE_F 0.05103103630798288f   // 384^-0.5
#define QSCALE (SCALE_F * 1.4426950408889634f)   // fold log2(e) for exp2 softmax

// ---------------------------------------------------------------------------
// Scratch (all GEMM inputs stored tf32-rounded + k-permuted)
// ---------------------------------------------------------------------------
__device__ float g_qt[(size_t)Mm * Cc];        // tf32 bits, c-permuted
__device__ float g_kt[(size_t)Mm * Cc];
__device__ float g_vt[(size_t)Mm * Cc];
__device__ float g_wq[(size_t)Cc * Cc];        // tf32 bits, k-permuted
__device__ float g_wk[(size_t)Cc * Cc];
__device__ float g_wv[(size_t)Cc * Cc];
__device__ float g_wp[(size_t)Cc * Cc];
__device__ float g_qp[(size_t)BH * TP * HDd];  // [bh][t][d] plain fp32 * QSCALE
__device__ float g_kp[(size_t)BH * TP * HDd];  // [bh][t][d-perm] tf32 bits
__device__ float g_vT[(size_t)BH * HDd * TP];  // [bh][d][t-perm] tf32 bits
__device__ float g_o [(size_t)Mm * Cc];        // [b,t,c-perm] tf32 bits

// ---------------------------------------------------------------------------
// helpers
// ---------------------------------------------------------------------------
__device__ __forceinline__ uint32_t f2tf32(float f) {
    uint32_t u;
    asm("cvt.rna.tf32.f32 %0, %1;" : "=r"(u) : "f"(f));
    return u;
}

__device__ __forceinline__ void mma_tf32(float c[4],
    uint32_t a0, uint32_t a1, uint32_t a2, uint32_t a3,
    uint32_t b0, uint32_t b1)
{
    asm volatile(
        "mma.sync.aligned.m16n8k8.row.col.f32.tf32.tf32.f32 "
        "{%0,%1,%2,%3}, {%4,%5,%6,%7}, {%8,%9}, {%0,%1,%2,%3};"
        : "+f"(c[0]), "+f"(c[1]), "+f"(c[2]), "+f"(c[3])
        : "r"(a0), "r"(a1), "r"(a2), "r"(a3), "r"(b0), "r"(b1));
}

__device__ __forceinline__ int pos16(int k) {
    return (k & 8) | ((k & 3) << 1) | ((k & 4) >> 2);
}
__device__ __forceinline__ int perm8(int n) {
    return (n >> 1) + ((n & 1) << 2);
}

__device__ __forceinline__ void cp_async16(uint32_t saddr, const void* gaddr) {
    asm volatile("cp.async.cg.shared.global [%0], [%1], 16;"
                 :: "r"(saddr), "l"(gaddr));
}

__device__ __forceinline__ uint32_t smem_u32(const void* p) {
    return (uint32_t)__cvta_generic_to_shared(p);
}

// ---------------------------------------------------------------------------
// conv + BN: outputs tf32-rounded, c-permuted (GEMM-A-ready)
// ---------------------------------------------------------------------------
__global__ void __launch_bounds__(256) convbn_kernel(
    const float* __restrict__ x,
    const float* __restrict__ cwq, const float* __restrict__ gq,
    const float* __restrict__ beq, const float* __restrict__ meq,
    const float* __restrict__ vaq,
    const float* __restrict__ cwk, const float* __restrict__ gk,
    const float* __restrict__ bek, const float* __restrict__ mek,
    const float* __restrict__ vak,
    const float* __restrict__ cwv, const float* __restrict__ gv,
    const float* __restrict__ bev, const float* __restrict__ mev,
    const float* __restrict__ vav)
{
    int idx = blockIdx.x * 256 + threadIdx.x;
    if (idx >= Mm * Cc) return;
    int c  = idx % Cc;
    int bt = idx / Cc;
    int t  = bt % Tt;
    int b  = bt / Tt;
    int y  = t / IMG_W;
    int xp = t % IMG_W;

    int odx = bt * Cc + ((c & ~15) | pos16(c & 15));

    float vals[9];
#pragma unroll
    for (int dy = 0; dy < 3; dy++) {
#pragma unroll
        for (int dx = 0; dx < 3; dx++) {
            int yy = y + dy - 1, xx = xp + dx - 1;
            bool in = (yy >= 0) && (yy < IMG_H) && (xx >= 0) && (xx < IMG_W);
            vals[dy * 3 + dx] =
                in ? x[((size_t)b * Tt + yy * IMG_W + xx) * Cc + c] : 0.f;
        }
    }
    {
        float acc = 0.f;
#pragma unroll
        for (int i = 0; i < 9; i++) acc += vals[i] * cwq[c * 9 + i];
        float inv = gq[c] * rsqrtf(vaq[c] + 1e-5f);
        g_qt[odx] = __uint_as_float(f2tf32(acc * inv + (beq[c] - meq[c] * inv)));
    }
    {
        float acc = 0.f;
#pragma unroll
        for (int i = 0; i < 9; i++) acc += vals[i] * cwk[c * 9 + i];
        float inv = gk[c] * rsqrtf(vak[c] + 1e-5f);
        g_kt[odx] = __uint_as_float(f2tf32(acc * inv + (bek[c] - mek[c] * inv)));
    }
    {
        float acc = 0.f;
#pragma unroll
        for (int i = 0; i < 9; i++) acc += vals[i] * cwv[c * 9 + i];
        float inv = gv[c] * rsqrtf(vav[c] + 1e-5f);
        g_vt[odx] = __uint_as_float(f2tf32(acc * inv + (bev[c] - mev[c] * inv)));
    }
}

// ---------------------------------------------------------------------------
// Weight conversion: tf32-rounded + k-permuted copies of the 4 weight mats
// ---------------------------------------------------------------------------
__global__ void __launch_bounds__(256) wconv_kernel(
    const float* __restrict__ wq, const float* __restrict__ wk,
    const float* __restrict__ wv, const float* __restrict__ wp)
{
    int i = blockIdx.x * 256 + threadIdx.x;
    if (i >= Cc * Cc) return;
    int k = i % Cc, n = i / Cc;
    int ip = n * Cc + ((k & ~15) | pos16(k & 15));
    g_wq[ip] = __uint_as_float(f2tf32(wq[i]));
    g_wk[ip] = __uint_as_float(f2tf32(wk[i]));
    g_wv[ip] = __uint_as_float(f2tf32(wv[i]));
    g_wp[ip] = __uint_as_float(f2tf32(wp[i]));
}

// ---------------------------------------------------------------------------
// GEMM core: 128x128 tile, NT, inputs pre-tf32+permuted in global.
// cp.async 4-stage ring, ONE barrier per BK=16 slab. 256 threads.
// ---------------------------------------------------------------------------
#define STRG 24
#define GEMM_SM (128 * STRG)
#define GEMM_DSMEM (8 * GEMM_SM * 4)   // 4 stages x (A+B) x 12KB = 98304 B

__device__ __forceinline__ void gemm128_async(
    const float* __restrict__ A, const float* __restrict__ B,
    int lda, int ldb, int K, int bm, int bn,
    uint32_t* As, uint32_t* Bs, float acc[4][4][4])
{
    const int tid  = threadIdx.x;
    const int lane = tid & 31;
    const int warp = tid >> 5;
    const int g    = lane >> 2;
    const int tq   = lane & 3;
    const int wm   = (warp & 1) * 64;
    const int wn   = (warp >> 1) * 32;
    const int lrow = tid >> 1;
    const int lkb  = (tid & 1) * 8;

    const float* Ag = A + (size_t)(bm + lrow) * lda + lkb;
    const float* Bg = B + (size_t)(bn + lrow) * ldb + lkb;
    uint32_t abase = smem_u32(As + lrow * STRG + lkb);
    uint32_t bbase = smem_u32(Bs + lrow * STRG + lkb);

    const int nslab = K >> 4;

#define GEMM_ISSUE(s) do {                                        \
        uint32_t _off = (uint32_t)(((s) & 3) * GEMM_SM * 4);      \
        const float* _ap = Ag + (s) * 16;                         \
        const float* _bp = Bg + (s) * 16;                         \
        cp_async16(abase + _off,      _ap);                       \
        cp_async16(abase + _off + 16, _ap + 4);                   \
        cp_async16(bbase + _off,      _bp);                       \
        cp_async16(bbase + _off + 16, _bp + 4);                   \
        asm volatile("cp.async.commit_group;");                   \
    } while (0)

    GEMM_ISSUE(0);
    GEMM_ISSUE(1);
    GEMM_ISSUE(2);

    for (int s = 0; s < nslab; s++) {
        asm volatile("cp.async.wait_group 2;");
        __syncthreads();
        const uint32_t* Ab = As + (s & 3) * GEMM_SM;
        const uint32_t* Bb = Bs + (s & 3) * GEMM_SM;
#pragma unroll
        for (int kk = 0; kk < 16; kk += 8) {
            uint32_t a[4][4];
#pragma unroll
            for (int ms = 0; ms < 4; ms++) {
                uint2 lo = *(const uint2*)&Ab[(wm + ms * 16 + g) * STRG + kk + 2 * tq];
                uint2 hi = *(const uint2*)&Ab[(wm + ms * 16 + g + 8) * STRG + kk + 2 * tq];
                a[ms][0] = lo.x; a[ms][2] = lo.y;
                a[ms][1] = hi.x; a[ms][3] = hi.y;
            }
#pragma unroll
            for (int j = 0; j < 4; j++) {
                uint2 bv = *(const uint2*)&Bb[(wn + j * 8 + g) * STRG + kk + 2 * tq];
#pragma unroll
                for (int ms = 0; ms < 4; ms++)
                    mma_tf32(acc[ms][j], a[ms][0], a[ms][1], a[ms][2], a[ms][3],
                             bv.x, bv.y);
            }
        }
        if (s + 3 < nslab) GEMM_ISSUE(s + 3);
        else asm volatile("cp.async.commit_group;");
    }
#undef GEMM_ISSUE
}

// ---------------------------------------------------------------------------
// Q/K/V projection (blockIdx.z selects q/k/v)
// ---------------------------------------------------------------------------
__global__ void __launch_bounds__(256) qkv_mma_kernel()
{
    extern __shared__ uint32_t dsm[];
    uint32_t* As = dsm;
    uint32_t* Bs = dsm + 4 * GEMM_SM;

    int which = blockIdx.z;
    const float* A = (which == 0) ? g_qt : (which == 1) ? g_kt : g_vt;
    const float* W = (which == 0) ? g_wq : (which == 1) ? g_wk : g_wv;

    int bm = blockIdx.x * 128, bn = blockIdx.y * 128;
    float acc[4][4][4] = {};
    gemm128_async(A, W, Cc, Cc, Cc, bm, bn, As, Bs, acc);

    int lane = threadIdx.x & 31, warp = threadIdx.x >> 5;
    int g = lane >> 2, tq = lane & 3;
    int wm = (warp & 1) * 64, wn = (warp >> 1) * 32;
    int h = (bn + wn) >> 6;

#pragma unroll
    for (int ms = 0; ms < 4; ms++) {
#pragma unroll
        for (int rr = 0; rr < 2; rr++) {
            int m = bm + wm + ms * 16 + g + rr * 8;
            int b = m / Tt, t = m - b * Tt;
            int bh = b * NHh + h;
            if (which == 0) {
                float* dst = g_qp + ((size_t)bh * TP + t) * HDd;
#pragma unroll
                for (int j = 0; j < 4; j++) {
                    int d = (bn + wn + j * 8 + 2 * tq) & 63;
                    *(float2*)(dst + d) = make_float2(
                        acc[ms][j][rr * 2 + 0] * QSCALE,
                        acc[ms][j][rr * 2 + 1] * QSCALE);
                }
            } else if (which == 1) {
                float* dst = g_kp + ((size_t)bh * TP + t) * HDd;
#pragma unroll
                for (int j = 0; j < 4; j++) {
                    int c0 = (bn + wn + j * 8 + 2 * tq) & 63;
                    int p0 = (c0 & 48) | pos16(c0 & 15);
                    int p1 = (c0 & 48) | pos16((c0 + 1) & 15);
                    dst[p0] = __uint_as_float(f2tf32(acc[ms][j][rr * 2 + 0]));
                    dst[p1] = __uint_as_float(f2tf32(acc[ms][j][rr * 2 + 1]));
                }
            } else {
                int tp = (t & ~15) | pos16(t & 15);
                float* dst = g_vT + (size_t)bh * HDd * TP + tp;
#pragma unroll
                for (int j = 0; j < 4; j++) {
                    int d = (bn + wn + j * 8 + 2 * tq) & 63;
                    dst[(size_t)d * TP] =
                        __uint_as_float(f2tf32(acc[ms][j][rr * 2 + 0]));
                    dst[(size_t)(d + 1) * TP] =
                        __uint_as_float(f2tf32(acc[ms][j][rr * 2 + 1]));
                }
            }
        }
    }
}

// ---------------------------------------------------------------------------
// Output projection (A = g_o tf32+permuted, B = g_wp)
// ---------------------------------------------------------------------------
__global__ void __launch_bounds__(256) proj_mma_kernel(
    const float* __restrict__ bias, float* __restrict__ out)
{
    extern __shared__ uint32_t dsm[];
    uint32_t* As = dsm;
    uint32_t* Bs = dsm + 4 * GEMM_SM;

    int bm = blockIdx.x * 128, bn = blockIdx.y * 128;
    float acc[4][4][4] = {};
    gemm128_async(g_o, g_wp, Cc, Cc, Cc, bm, bn, As, Bs, acc);

    int lane = threadIdx.x & 31, warp = threadIdx.x >> 5;
    int g = lane >> 2, tq = lane & 3;
    int wm = (warp & 1) * 64, wn = (warp >> 1) * 32;
#pragma unroll
    for (int ms = 0; ms < 4; ms++) {
#pragma unroll
        for (int rr = 0; rr < 2; rr++) {
            int m = bm + wm + ms * 16 + g + rr * 8;
#pragma unroll
            for (int j = 0; j < 4; j++) {
                int n = bn + wn + j * 8 + 2 * tq;
                float2 bb = *(const float2*)(bias + n);
                *(float2*)(out + (size_t)m * Cc + n) = make_float2(
                    acc[ms][j][rr * 2 + 0] + bb.x,
                    acc[ms][j][rr * 2 + 1] + bb.y);
            }
        }
    }
}

// ---------------------------------------------------------------------------
// Flash attention. Block = (bh, 128 q rows), 256 threads (8 warps x 16 rows).
// Epilogue writes g_o tf32-rounded + c-permuted (proj-GEMM-ready).
// ---------------------------------------------------------------------------
#define STRF 72
#define FBUF (64 * STRF)

__global__ void __launch_bounds__(256) flash_kernel()
{
    __shared__ uint32_t Ks[2 * FBUF];
    __shared__ uint32_t Vs[2 * FBUF];

    int bh = blockIdx.y;
    int q0 = blockIdx.x * 128;
    int tid = threadIdx.x, lane = tid & 31, warp = tid >> 5;
    int g = lane >> 2, tq = lane & 3;

    const float* Qb = g_qp + (size_t)bh * TP * HDd;
    const float* Kb = g_kp + (size_t)bh * TP * HDd;
    const float* Vb = g_vT + (size_t)bh * HDd * TP;

    const int lrow = tid >> 2;            // 0..63
    const int lq   = (tid & 3) * 16;      // segment start (words)
    const int krow = (lrow & ~7) | perm8(lrow & 7);

    const float* ksrc = Kb + (size_t)krow * HDd + lq;
    const float* vsrc = Vb + (size_t)lrow * TP + lq;
    uint32_t kbase = smem_u32(Ks + lrow * STRF + lq);
    uint32_t vbase = smem_u32(Vs + lrow * STRF + lq);

    auto issue_chunk = [&](int ct) {
        uint32_t off = (ct & 1) * (FBUF * 4);
        const float* kp = ksrc + (size_t)ct * 64 * HDd;
        const float* vp = vsrc + ct * 64;
#pragma unroll
        for (int i = 0; i < 4; i++) {
            cp_async16(kbase + off + i * 16, kp + i * 4);
            cp_async16(vbase + off + i * 16, vp + i * 4);
        }
        asm volatile("cp.async.commit_group;");
    };

    uint32_t qf[8][4];
    {
        int r0i = min(q0 + warp * 16 + g, Tt - 1);
        int r1i = min(q0 + warp * 16 + g + 8, Tt - 1);
        const float* r0 = Qb + (size_t)r0i * HDd;
        const float* r1 = Qb + (size_t)r1i * HDd;
#pragma unroll
        for (int k8 = 0; k8 < 8; k8++) {
            qf[k8][0] = f2tf32(r0[k8 * 8 + tq]);
            qf[k8][2] = f2tf32(r0[k8 * 8 + tq + 4]);
            qf[k8][1] = f2tf32(r1[k8 * 8 + tq]);
            qf[k8][3] = f2tf32(r1[k8 * 8 + tq + 4]);
        }
    }

    issue_chunk(0);
    issue_chunk(1);

    float oacc[8][4];
#pragma unroll
    for (int j = 0; j < 8; j++)
#pragma unroll
        for (int i = 0; i < 4; i++) oacc[j][i] = 0.f;
    float m0 = -1e30f, m1 = -1e30f, l0 = 0.f, l1 = 0.f;

    for (int ct = 0; ct < 13; ct++) {
        if (ct < 12) asm volatile("cp.async.wait_group 1;");
        else         asm volatile("cp.async.wait_group 0;");
        __syncthreads();

        const uint32_t* Kbuf = Ks + (ct & 1) * FBUF;
        const uint32_t* Vbuf = Vs + (ct & 1) * FBUF;

        float sacc[8][4];
#pragma unroll
        for (int j = 0; j < 8; j++)
#pragma unroll
            for (int i = 0; i < 4; i++) sacc[j][i] = 0.f;
#pragma unroll
        for (int kk = 0; kk < 64; kk += 8) {
#pragma unroll
            for (int j = 0; j < 8; j++) {
                uint2 bv = *(const uint2*)&Kbuf[(j * 8 + g) * STRF + kk + 2 * tq];
                mma_tf32(sacc[j], qf[kk >> 3][0], qf[kk >> 3][1],
                         qf[kk >> 3][2], qf[kk >> 3][3], bv.x, bv.y);
            }
        }

        if (ct == 12) {
#pragma unroll
            for (int j = 2; j < 8; j++)
#pragma unroll
                for (int i = 0; i < 4; i++) sacc[j][i] = -1e30f;
        }

        float t0m = -1e30f, t1m = -1e30f;
#pragma unroll
        for (int j = 0; j < 8; j++) {
            t0m = fmaxf(t0m, fmaxf(sacc[j][0], sacc[j][1]));
            t1m = fmaxf(t1m, fmaxf(sacc[j][2], sacc[j][3]));
        }
        t0m = fmaxf(t0m, __shfl_xor_sync(0xffffffffu, t0m, 1));
        t0m = fmaxf(t0m, __shfl_xor_sync(0xffffffffu, t0m, 2));
        t1m = fmaxf(t1m, __shfl_xor_sync(0xffffffffu, t1m, 1));
        t1m = fmaxf(t1m, __shfl_xor_sync(0xffffffffu, t1m, 2));
        float mn0 = fmaxf(m0, t0m), mn1 = fmaxf(m1, t1m);
        float sc0 = exp2f(m0 - mn0), sc1 = exp2f(m1 - mn1);
        m0 = mn0; m1 = mn1;
        l0 *= sc0; l1 *= sc1;
        float ps0 = 0.f, ps1 = 0.f;
#pragma unroll
        for (int j = 0; j < 8; j++) {
            oacc[j][0] *= sc0; oacc[j][1] *= sc0;
            oacc[j][2] *= sc1; oacc[j][3] *= sc1;
            sacc[j][0] = exp2f(sacc[j][0] - mn0);
            sacc[j][1] = exp2f(sacc[j][1] - mn0);
            sacc[j][2] = exp2f(sacc[j][2] - mn1);
            sacc[j][3] = exp2f(sacc[j][3] - mn1);
            ps0 += sacc[j][0] + sacc[j][1];
            ps1 += sacc[j][2] + sacc[j][3];
        }
        l0 += ps0; l1 += ps1;

#pragma unroll
        for (int kk = 0; kk < 64; kk += 8) {
            int jj = kk >> 3;
            uint32_t pa0 = f2tf32(sacc[jj][0]);
            uint32_t pa1 = f2tf32(sacc[jj][2]);
            uint32_t pa2 = f2tf32(sacc[jj][1]);
            uint32_t pa3 = f2tf32(sacc[jj][3]);
#pragma unroll
            for (int j = 0; j < 8; j++) {
                uint2 bv = *(const uint2*)&Vbuf[(j * 8 + g) * STRF + kk + 2 * tq];
                mma_tf32(oacc[j], pa0, pa1, pa2, pa3, bv.x, bv.y);
            }
        }

        __syncthreads();
        if (ct + 2 < 13) issue_chunk(ct + 2);
    }

    l0 += __shfl_xor_sync(0xffffffffu, l0, 1);
    l0 += __shfl_xor_sync(0xffffffffu, l0, 2);
    l1 += __shfl_xor_sync(0xffffffffu, l1, 1);
    l1 += __shfl_xor_sync(0xffffffffu, l1, 2);
    float inv0 = 1.f / l0, inv1 = 1.f / l1;

    int b = bh / NHh, h = bh - (bh / NHh) * NHh;
    int r0g = q0 + warp * 16 + g, r1g = r0g + 8;
    // g_o written tf32-rounded + c-permuted (proj GEMM input format)
    if (r0g < Tt) {
        float* dst = g_o + ((size_t)b * Tt + r0g) * Cc + h * HDd;
#pragma unroll
        for (int j = 0; j < 8; j++) {
            int c0 = j * 8 + 2 * tq;
            int p0 = (c0 & 48) | pos16(c0 & 15);
            int p1 = (c0 & 48) | pos16((c0 + 1) & 15);
            dst[p0] = __uint_as_float(f2tf32(oacc[j][0] * inv0));
            dst[p1] = __uint_as_float(f2tf32(oacc[j][1] * inv0));
        }
    }
    if (r1g < Tt) {
        float* dst = g_o + ((size_t)b * Tt + r1g) * Cc + h * HDd;
#pragma unroll
        for (int j = 0; j < 8; j++) {
            int c0 = j * 8 + 2 * tq;
            int p0 = (c0 & 48) | pos16(c0 & 15);
            int p1 = (c0 & 48) | pos16((c0 + 1) & 15);
            dst[p0] = __uint_as_float(f2tf32(oacc[j][2] * inv1));
            dst[p1] = __uint_as_float(f2tf32(oacc[j][3] * inv1));
        }
    }
}

// ---------------------------------------------------------------------------
// kernel_launch
// ---------------------------------------------------------------------------
extern "C" void kernel_launch(void* const* d_in, const int* in_sizes, int n_in,
                              void* d_out, int out_size)
{
    int base = 1;
    if (n_in >= 3 && in_sizes[1] == 1 && in_sizes[2] == 1) base = 3;

    const float* x = (const float*)d_in[0];
    const float* cw[3];
    const float* ga[3];
    const float* be[3];
    const float* me[3];
    const float* va[3];
    for (int i = 0; i < 3; i++) {
        cw[i] = (const float*)d_in[base + 5 * i + 0];
        ga[i] = (const float*)d_in[base + 5 * i + 1];
        be[i] = (const float*)d_in[base + 5 * i + 2];
        me[i] = (const float*)d_in[base + 5 * i + 3];
        va[i] = (const float*)d_in[base + 5 * i + 4];
    }
    const float* w_q    = (const float*)d_in[base + 15];
    const float* w_k    = (const float*)d_in[base + 16];
    const float* w_v    = (const float*)d_in[base + 17];
    const float* w_proj = (const float*)d_in[base + 18];
    const float* b_proj = (const float*)d_in[base + 19];
    float* out = (float*)d_out;

    static int attr_done = 0;
    if (!attr_done) {
        cudaFuncSetAttribute(qkv_mma_kernel,
                             cudaFuncAttributeMaxDynamicSharedMemorySize,
                             GEMM_DSMEM);
        cudaFuncSetAttribute(proj_mma_kernel,
                             cudaFuncAttributeMaxDynamicSharedMemorySize,
                             GEMM_DSMEM);
        attr_done = 1;
    }

    wconv_kernel<<<(Cc * Cc + 255) / 256, 256>>>(w_q, w_k, w_v, w_proj);

    convbn_kernel<<<(Mm * Cc + 255) / 256, 256>>>(
        x,
        cw[0], ga[0], be[0], me[0], va[0],
        cw[1], ga[1], be[1], me[1], va[1],
        cw[2], ga[2], be[2], me[2], va[2]);

    qkv_mma_kernel<<<dim3(Mm / 128, Cc / 128, 3), 256, GEMM_DSMEM>>>();

    flash_kernel<<<dim3(7, BH), 256>>>();

    proj_mma_kernel<<<dim3(Mm / 128, Cc / 128), 256, GEMM_DSMEM>>>(b_proj, out);
}